// round 9
// baseline (speedup 1.0000x reference)
#include <cuda_runtime.h>
#include <math_constants.h>
#include <cstdint>
#include <cstddef>

// Problem constants
#define HH 8
#define KD 64
#define VD 64
#define KNN 128
#define DM 512
#define FCD 2048
#define NB 4
#define SSQ 1024
#define EPS 1e-5f

// ---------------- scratch (single __device__ array, no allocations) ----------------
constexpr size_t OFF_GDEC = 0;
constexpr size_t OFF_GENC = OFF_GDEC + (size_t)SSQ * SSQ;
constexpr size_t OFF_K    = OFF_GENC + (size_t)SSQ * SSQ;
constexpr size_t OFF_V    = OFF_K   + (size_t)HH * NB * SSQ * KD;
constexpr size_t OFF_Q    = OFF_V   + (size_t)HH * NB * SSQ * VD;
constexpr size_t OFF_CTX  = OFF_Q   + (size_t)HH * NB * SSQ * KD;
constexpr size_t OFF_H    = OFF_CTX + (size_t)NB * SSQ * DM;
constexpr size_t OFF_H2   = OFF_H   + (size_t)NB * SSQ * DM;
constexpr size_t OFF_T    = OFF_H2  + (size_t)NB * SSQ * DM;
constexpr size_t OFF_ATT  = OFF_T   + (size_t)NB * SSQ * FCD;
constexpr size_t SCRATCH_TOTAL = OFF_ATT + (size_t)HH * NB * SSQ * SSQ;

__device__ float g_scratch[SCRATCH_TOTAL];

// ---------------- TF32 helpers ----------------
__device__ __forceinline__ uint32_t f2tf32(float f) {
    uint32_t o;
    asm("cvt.rna.tf32.f32 %0, %1;" : "=r"(o) : "f"(f));
    return o;
}

__device__ __forceinline__ void mma_tf32v(float c[4],
                                          uint32_t a0, uint32_t a1, uint32_t a2, uint32_t a3,
                                          uint32_t b0, uint32_t b1)
{
    asm volatile(
        "mma.sync.aligned.m16n8k8.row.col.f32.tf32.tf32.f32 "
        "{%0,%1,%2,%3}, {%4,%5,%6,%7}, {%8,%9}, {%0,%1,%2,%3};"
        : "+f"(c[0]), "+f"(c[1]), "+f"(c[2]), "+f"(c[3])
        : "r"(a0), "r"(a1), "r"(a2), "r"(a3),
          "r"(b0), "r"(b1));
}

// ---------------- batched TF32 tensor-core GEMM, fragment-order smem ----------------
// C = alpha*A@B(^T) [+bias][relu][+resid]
// Block tile 128(M) x 64(N), K-tile 16, 256 threads = 8 warps (4x2),
// warp tile 32x32 = 2x4 m16n8k8 fragments, double-buffered smem.
// Smem holds tiles permuted into mma fragment order:
//   A: slot = ((m_tile*2 + k_step)*32 + gid*4 + tg)*4 + frag, frag in [0,4) -> LDS.128
//   B: slot = ((n_tile*2 + k_step)*32 + gid*4 + tg)*2 + frag, frag in [0,2) -> LDS.64
// Requirements: M % 128 == 0, Nc % 64 == 0, Kc % 16 == 0 (true for all calls).
#define A_FRAG_WORDS 2048   // 16 blocks * 32 lanes * 4
#define B_FRAG_WORDS 1024   // 16 blocks * 32 lanes * 2

__global__ __launch_bounds__(256) void gemm_k(
    const float* __restrict__ A, const float* __restrict__ B, float* __restrict__ C,
    int Nc, int Kc, int ldc,
    long long sAo, long long sAi, long long sBo, long long sBi,
    long long sCo, long long sCi, int Bi,
    const float* __restrict__ bias, long long sBias,
    const float* __restrict__ resid, int ldr,
    float alpha, int transB, int relu)
{
    __shared__ uint32_t As[2][A_FRAG_WORDS];
    __shared__ uint32_t Bs[2][B_FRAG_WORDS];

    int z = blockIdx.z;
    int zo = z / Bi, zi = z - zo * Bi;
    A += (size_t)zo * sAo + (size_t)zi * sAi;
    B += (size_t)zo * sBo + (size_t)zi * sBi;
    C += (size_t)zo * sCo + (size_t)zi * sCi;
    const float* biasp = bias ? (bias + (size_t)zo * sBias) : nullptr;

    int bn0 = blockIdx.x * 64;
    int bm0 = blockIdx.y * 128;
    int t = threadIdx.x;
    int lane = t & 31, w = t >> 5;
    int wm = w >> 1, wn = w & 1;          // 4 x 2 warp grid
    int gid = lane >> 2, tg = lane & 3;

    // ---- loader mappings ----
    // A: thread handles rows (t>>2) and (t>>2)+64, float4 at k-quad (t&3)
    int a_row0 = t >> 2, a_kq = t & 3;
    int a_row1 = a_row0 + 64;
    auto a_base = [&](int m, int kq) {
        int m_tile = m >> 4;
        int gg = m & 7;
        int fr = (m >> 3) & 1;
        int k_step = kq >> 1;
        int f2 = kq & 1;
        int frag = fr + 2 * f2;
        return ((m_tile * 2 + k_step) * 32 + gg * 4) * 4 + frag;
    };
    int aS0 = a_base(a_row0, a_kq);
    int aS1 = a_base(a_row1, a_kq);

    // B non-trans: kk = t>>4 in [0,16), float4 over n at nq = t&15
    int b_kk = t >> 4, b_nq = t & 15;
    int bS_nt;
    {
        int n = b_nq * 4;                 // element j -> n+j, gid gg+j (gg in {0,4})
        int n_tile = n >> 3;
        int gg = n & 7;
        int k_step = b_kk >> 3;
        int tgb = b_kk & 3;
        int f = (b_kk >> 2) & 1;
        bS_nt = ((n_tile * 2 + k_step) * 32 + gg * 4 + tgb) * 2 + f;
        // element j: addr = bS_nt + j*8
    }
    // B trans: n = t>>2, float4 over k at kq = t&3
    int bt_n = t >> 2, bt_kq = t & 3;
    int btS;
    {
        int n_tile = bt_n >> 3;
        int gg = bt_n & 7;
        int k_step = bt_kq >> 1;
        int f = bt_kq & 1;
        btS = ((n_tile * 2 + k_step) * 32 + gg * 4) * 2 + f;
        // element j (tg=j): addr = btS + j*2
    }

    float acc[2][4][4] = {};

    // ---- prologue: tile 0 ----
    {
        float4 v0 = *(const float4*)&A[(size_t)(bm0 + a_row0) * Kc + a_kq * 4];
        float4 v1 = *(const float4*)&A[(size_t)(bm0 + a_row1) * Kc + a_kq * 4];
        As[0][aS0 + 0]  = f2tf32(v0.x); As[0][aS0 + 4]  = f2tf32(v0.y);
        As[0][aS0 + 8]  = f2tf32(v0.z); As[0][aS0 + 12] = f2tf32(v0.w);
        As[0][aS1 + 0]  = f2tf32(v1.x); As[0][aS1 + 4]  = f2tf32(v1.y);
        As[0][aS1 + 8]  = f2tf32(v1.z); As[0][aS1 + 12] = f2tf32(v1.w);
        if (!transB) {
            float4 v = *(const float4*)&B[(size_t)b_kk * Nc + bn0 + b_nq * 4];
            Bs[0][bS_nt + 0]  = f2tf32(v.x); Bs[0][bS_nt + 8]  = f2tf32(v.y);
            Bs[0][bS_nt + 16] = f2tf32(v.z); Bs[0][bS_nt + 24] = f2tf32(v.w);
        } else {
            float4 v = *(const float4*)&B[(size_t)(bn0 + bt_n) * Kc + bt_kq * 4];
            Bs[0][btS + 0] = f2tf32(v.x); Bs[0][btS + 2] = f2tf32(v.y);
            Bs[0][btS + 4] = f2tf32(v.z); Bs[0][btS + 6] = f2tf32(v.w);
        }
    }
    __syncthreads();

    // mainloop fragment-load bases
    int aL0 = (((wm * 2 + 0) * 2) * 32 + lane) * 4;   // k_step adds 128 words
    int aL1 = (((wm * 2 + 1) * 2) * 32 + lane) * 4;
    int bL[4];
    #pragma unroll
    for (int nj = 0; nj < 4; nj++)
        bL[nj] = (((wn * 4 + nj) * 2) * 32 + lane) * 2;  // k_step adds 64 words

    int nT = Kc >> 4;
    int cur = 0;
    for (int tt = 0; tt < nT; tt++) {
        float4 pa0, pa1, pb;
        bool has = (tt + 1) < nT;
        if (has) {
            int k0 = (tt + 1) << 4;
            pa0 = *(const float4*)&A[(size_t)(bm0 + a_row0) * Kc + k0 + a_kq * 4];
            pa1 = *(const float4*)&A[(size_t)(bm0 + a_row1) * Kc + k0 + a_kq * 4];
            if (!transB)
                pb = *(const float4*)&B[(size_t)(k0 + b_kk) * Nc + bn0 + b_nq * 4];
            else
                pb = *(const float4*)&B[(size_t)(bn0 + bt_n) * Kc + k0 + bt_kq * 4];
        }

        const uint32_t* Ac = As[cur];
        const uint32_t* Bc = Bs[cur];
        #pragma unroll
        for (int k_step = 0; k_step < 2; k_step++) {
            uint4 af0 = *(const uint4*)&Ac[aL0 + k_step * 128];
            uint4 af1 = *(const uint4*)&Ac[aL1 + k_step * 128];
            uint2 bf0 = *(const uint2*)&Bc[bL[0] + k_step * 64];
            uint2 bf1 = *(const uint2*)&Bc[bL[1] + k_step * 64];
            uint2 bf2 = *(const uint2*)&Bc[bL[2] + k_step * 64];
            uint2 bf3 = *(const uint2*)&Bc[bL[3] + k_step * 64];
            mma_tf32v(acc[0][0], af0.x, af0.y, af0.z, af0.w, bf0.x, bf0.y);
            mma_tf32v(acc[0][1], af0.x, af0.y, af0.z, af0.w, bf1.x, bf1.y);
            mma_tf32v(acc[0][2], af0.x, af0.y, af0.z, af0.w, bf2.x, bf2.y);
            mma_tf32v(acc[0][3], af0.x, af0.y, af0.z, af0.w, bf3.x, bf3.y);
            mma_tf32v(acc[1][0], af1.x, af1.y, af1.z, af1.w, bf0.x, bf0.y);
            mma_tf32v(acc[1][1], af1.x, af1.y, af1.z, af1.w, bf1.x, bf1.y);
            mma_tf32v(acc[1][2], af1.x, af1.y, af1.z, af1.w, bf2.x, bf2.y);
            mma_tf32v(acc[1][3], af1.x, af1.y, af1.z, af1.w, bf3.x, bf3.y);
        }

        if (has) {
            int nxt = cur ^ 1;
            As[nxt][aS0 + 0]  = f2tf32(pa0.x); As[nxt][aS0 + 4]  = f2tf32(pa0.y);
            As[nxt][aS0 + 8]  = f2tf32(pa0.z); As[nxt][aS0 + 12] = f2tf32(pa0.w);
            As[nxt][aS1 + 0]  = f2tf32(pa1.x); As[nxt][aS1 + 4]  = f2tf32(pa1.y);
            As[nxt][aS1 + 8]  = f2tf32(pa1.z); As[nxt][aS1 + 12] = f2tf32(pa1.w);
            if (!transB) {
                Bs[nxt][bS_nt + 0]  = f2tf32(pb.x); Bs[nxt][bS_nt + 8]  = f2tf32(pb.y);
                Bs[nxt][bS_nt + 16] = f2tf32(pb.z); Bs[nxt][bS_nt + 24] = f2tf32(pb.w);
            } else {
                Bs[nxt][btS + 0] = f2tf32(pb.x); Bs[nxt][btS + 2] = f2tf32(pb.y);
                Bs[nxt][btS + 4] = f2tf32(pb.z); Bs[nxt][btS + 6] = f2tf32(pb.w);
            }
            __syncthreads();
            cur = nxt;
        }
    }

    // ---- epilogue ----
    // C fragment layout: c0:(g,2tg) c1:(g,2tg+1) c2:(g+8,2tg) c3:(g+8,2tg+1)
    int mb = wm * 32, nb = wn * 32;
    #pragma unroll
    for (int mi = 0; mi < 2; mi++) {
        int r0 = bm0 + mb + mi * 16 + gid;
        #pragma unroll
        for (int nj = 0; nj < 4; nj++) {
            int cc = bn0 + nb + nj * 8 + 2 * tg;
            float b0 = 0.f, b1 = 0.f;
            if (biasp) { b0 = biasp[cc]; b1 = biasp[cc + 1]; }
            #pragma unroll
            for (int half = 0; half < 2; half++) {
                int row = r0 + half * 8;
                float vx = acc[mi][nj][half * 2 + 0] * alpha + b0;
                float vy = acc[mi][nj][half * 2 + 1] * alpha + b1;
                if (relu) { vx = fmaxf(vx, 0.f); vy = fmaxf(vy, 0.f); }
                if (resid) {
                    float2 r = *(const float2*)&resid[(size_t)row * ldr + cc];
                    vx += r.x; vy += r.y;
                }
                float2 o; o.x = vx; o.y = vy;
                *(float2*)&C[(size_t)row * ldc + cc] = o;
            }
        }
    }
}

// ---------------- row softmax (graph preprocessing), rows of length SSQ ----------------
__global__ __launch_bounds__(256) void row_softmax_k(const float* __restrict__ in,
                                                     float* __restrict__ out)
{
    __shared__ float sh[8];
    int row = blockIdx.x;
    int t = threadIdx.x;
    int lane = t & 31, w = t >> 5;
    const float* rin = in + (size_t)row * SSQ;
    float* rout = out + (size_t)row * SSQ;

    float v[4];
    #pragma unroll
    for (int i = 0; i < 4; i++) v[i] = rin[t + i * 256];

    float m = fmaxf(fmaxf(v[0], v[1]), fmaxf(v[2], v[3]));
    #pragma unroll
    for (int o = 16; o; o >>= 1) m = fmaxf(m, __shfl_xor_sync(0xffffffffu, m, o));
    if (lane == 0) sh[w] = m;
    __syncthreads();
    m = sh[0];
    #pragma unroll
    for (int i = 1; i < 8; i++) m = fmaxf(m, sh[i]);
    __syncthreads();

    float e[4]; float s = 0.f;
    #pragma unroll
    for (int i = 0; i < 4; i++) { e[i] = expf(v[i] - m); s += e[i]; }
    #pragma unroll
    for (int o = 16; o; o >>= 1) s += __shfl_xor_sync(0xffffffffu, s, o);
    if (lane == 0) sh[w] = s;
    __syncthreads();
    s = 0.f;
    #pragma unroll
    for (int i = 0; i < 8; i++) s += sh[i];
    float inv = 1.0f / s;
    #pragma unroll
    for (int i = 0; i < 4; i++) rout[t + i * 256] = e[i] * inv;
}

// ---------------- fused: causal mask + exact top-KNN threshold + softmax + graph blend ----------------
__device__ __forceinline__ unsigned f2key(float f) {
    unsigned u = __float_as_uint(f);
    return (u & 0x80000000u) ? ~u : (u | 0x80000000u);
}

__global__ __launch_bounds__(256) void attn_post_k(float* __restrict__ att,
                                                   const float* __restrict__ graph,
                                                   int masked, float gw)
{
    __shared__ float sredf[8];
    __shared__ unsigned scount[2][8];

    int q = blockIdx.x, n = blockIdx.y, h = blockIdx.z;
    float* row = att + (((size_t)(h * NB + n)) * SSQ + q) * SSQ;
    const float* grow = graph + (size_t)q * SSQ;
    int L = masked ? (q + 1) : SSQ;

    int t = threadIdx.x;
    int lane = t & 31, w = t >> 5;

    float v[4]; unsigned key[4]; bool valid[4];
    #pragma unroll
    for (int i = 0; i < 4; i++) {
        int idx = t + i * 256;
        valid[i] = idx < L;
        v[i] = valid[i] ? row[idx] : -CUDART_INF_F;
        key[i] = valid[i] ? f2key(v[i]) : 0u;
    }

    unsigned threshKey = 0;
    if (L > KNN) {
        unsigned lo = 0u, hi = 0xFFFFFFFFu;
        unsigned it = 0;
        while (lo < hi) {
            unsigned mid = (unsigned)((((unsigned long long)lo + (unsigned long long)hi + 1ull)) >> 1);
            unsigned c = 0;
            #pragma unroll
            for (int i = 0; i < 4; i++) c += (key[i] >= mid) ? 1u : 0u;
            #pragma unroll
            for (int o = 16; o; o >>= 1) c += __shfl_xor_sync(0xffffffffu, c, o);
            unsigned* sc = scount[it & 1];
            if (lane == 0) sc[w] = c;
            __syncthreads();
            unsigned cnt = 0;
            #pragma unroll
            for (int i = 0; i < 8; i++) cnt += sc[i];
            if (cnt >= KNN) lo = mid; else hi = mid - 1u;
            it++;
        }
        threshKey = lo;
    }

    bool kept[4];
    #pragma unroll
    for (int i = 0; i < 4; i++)
        kept[i] = valid[i] && (L <= KNN || key[i] >= threshKey);

    float m = -CUDART_INF_F;
    #pragma unroll
    for (int i = 0; i < 4; i++) if (kept[i]) m = fmaxf(m, v[i]);
    #pragma unroll
    for (int o = 16; o; o >>= 1) m = fmaxf(m, __shfl_xor_sync(0xffffffffu, m, o));
    __syncthreads();   // protect sredf reuse vs earlier scount reads
    if (lane == 0) sredf[w] = m;
    __syncthreads();
    m = sredf[0];
    #pragma unroll
    for (int i = 1; i < 8; i++) m = fmaxf(m, sredf[i]);
    __syncthreads();

    float e[4]; float s = 0.f;
    #pragma unroll
    for (int i = 0; i < 4; i++) {
        e[i] = kept[i] ? expf(v[i] - m) : 0.f;
        s += e[i];
    }
    #pragma unroll
    for (int o = 16; o; o >>= 1) s += __shfl_xor_sync(0xffffffffu, s, o);
    if (lane == 0) sredf[w] = s;
    __syncthreads();
    s = 0.f;
    #pragma unroll
    for (int i = 0; i < 8; i++) s += sredf[i];
    float inv = 1.0f / s;

    float og = 1.0f - gw;
    #pragma unroll
    for (int i = 0; i < 4; i++) {
        int idx = t + i * 256;
        row[idx] = gw * grow[idx] + og * (e[i] * inv);
    }
}

// ---------------- LayerNorm over rows of DM=512 (elementwise_affine=False) ----------------
__global__ __launch_bounds__(128) void layernorm_k(const float* __restrict__ in,
                                                   float* __restrict__ out)
{
    __shared__ float sh[4];
    int row = blockIdx.x;
    int t = threadIdx.x;
    int lane = t & 31, w = t >> 5;
    const float* rin = in + (size_t)row * DM;
    float* rout = out + (size_t)row * DM;

    float v[4];
    #pragma unroll
    for (int i = 0; i < 4; i++) v[i] = rin[t + i * 128];

    float s = v[0] + v[1] + v[2] + v[3];
    #pragma unroll
    for (int o = 16; o; o >>= 1) s += __shfl_xor_sync(0xffffffffu, s, o);
    if (lane == 0) sh[w] = s;
    __syncthreads();
    s = sh[0] + sh[1] + sh[2] + sh[3];
    float mean = s * (1.0f / DM);
    __syncthreads();

    float sq = 0.f;
    #pragma unroll
    for (int i = 0; i < 4; i++) { float d = v[i] - mean; sq += d * d; }
    #pragma unroll
    for (int o = 16; o; o >>= 1) sq += __shfl_xor_sync(0xffffffffu, sq, o);
    if (lane == 0) sh[w] = sq;
    __syncthreads();
    sq = sh[0] + sh[1] + sh[2] + sh[3];
    float var = sq * (1.0f / DM);
    float inv = rsqrtf(var + EPS);

    #pragma unroll
    for (int i = 0; i < 4; i++) rout[t + i * 128] = (v[i] - mean) * inv;
}

// ---------------- host-side helpers ----------------
static inline void gemm(const float* A, const float* B, float* C,
                        int M, int Nc, int Kc, int ldc,
                        long long sAo, long long sAi, long long sBo, long long sBi,
                        long long sCo, long long sCi, int Bo, int Bi,
                        const float* bias, long long sBias,
                        const float* resid, int ldr,
                        float alpha, int transB, int relu)
{
    dim3 grid(Nc / 64, M / 128, Bo * Bi), block(256);
    gemm_k<<<grid, block>>>(A, B, C, Nc, Kc, ldc, sAo, sAi, sBo, sBi, sCo, sCi, Bi,
                            bias, sBias, resid, ldr, alpha, transB, relu);
}

extern "C" void kernel_launch(void* const* d_in, const int* in_sizes, int n_in,
                              void* d_out, int out_size)
{
    (void)in_sizes; (void)n_in; (void)out_size;
    const float* z        = (const float*)d_in[0];
    const float* y        = (const float*)d_in[1];
    const float* graphDec = (const float*)d_in[2];
    const float* graphEnc = (const float*)d_in[3];
    const float* dec_Wk   = (const float*)d_in[4];
    const float* dec_bk   = (const float*)d_in[5];
    const float* dec_Wv   = (const float*)d_in[6];
    const float* dec_bv   = (const float*)d_in[7];
    const float* dec_Wo   = (const float*)d_in[8];
    const float* dec_bo   = (const float*)d_in[9];
    const float* enc_Wk   = (const float*)d_in[10];
    const float* enc_bk   = (const float*)d_in[11];
    const float* enc_Wq   = (const float*)d_in[12];
    const float* enc_bq   = (const float*)d_in[13];
    const float* enc_Wv   = (const float*)d_in[14];
    const float* enc_bv   = (const float*)d_in[15];
    const float* enc_Wo   = (const float*)d_in[16];
    const float* enc_bo   = (const float*)d_in[17];
    const float* fc_W1    = (const float*)d_in[18];
    const float* fc_b1    = (const float*)d_in[19];
    const float* fc_W2    = (const float*)d_in[20];
    const float* fc_b2    = (const float*)d_in[21];
    float* out = (float*)d_out;

    float* sc = nullptr;
    cudaGetSymbolAddress((void**)&sc, g_scratch);
    float* gdec = sc + OFF_GDEC;
    float* genc = sc + OFF_GENC;
    float* gK   = sc + OFF_K;
    float* gV   = sc + OFF_V;
    float* gQ   = sc + OFF_Q;
    float* gCtx = sc + OFF_CTX;
    float* gH   = sc + OFF_H;
    float* gH2  = sc + OFF_H2;
    float* gT   = sc + OFF_T;
    float* gAtt = sc + OFF_ATT;

    const int M = NB * SSQ;               // 4096
    const long long sKh = (long long)NB * SSQ * KD;  // per-head stride in K/V/Q
    const long long sKn = (long long)SSQ * KD;       // per-batch stride
    const long long sAh = (long long)NB * SSQ * SSQ; // att per-head
    const long long sAn = (long long)SSQ * SSQ;      // att per-batch
    const float inv_scale = 0.125f;       // 1/sqrt(64)

    // 0) graph row-softmax
    row_softmax_k<<<SSQ, 256>>>(graphDec, gdec);
    row_softmax_k<<<SSQ, 256>>>(graphEnc, genc);

    // ---------- stage 1: masked decoder self-attention on y ----------
    gemm(y, dec_Wk, gK, M, KD, DM, KD, 0, 0, (long long)DM * KD, 0, sKh, 0, HH, 1,
         dec_bk, KD, nullptr, 0, 1.0f, 0, 0);
    gemm(y, dec_Wv, gV, M, VD, DM, VD, 0, 0, (long long)DM * VD, 0, sKh, 0, HH, 1,
         dec_bv, VD, nullptr, 0, 1.0f, 0, 0);
    gemm(gK, gK, gAtt, SSQ, SSQ, KD, SSQ, sKh, sKn, sKh, sKn, sAh, sAn, HH, NB,
         nullptr, 0, nullptr, 0, inv_scale, 1, 0);
    attn_post_k<<<dim3(SSQ, NB, HH), 256>>>(gAtt, gdec, 1, 0.5f);
    gemm(gAtt, gV, gCtx, SSQ, VD, SSQ, DM, sAh, sAn, sKh, sKn, (long long)VD, (long long)SSQ * DM,
         HH, NB, nullptr, 0, nullptr, 0, 1.0f, 0, 0);
    gemm(gCtx, dec_Wo, gH, M, DM, DM, DM, 0, 0, 0, 0, 0, 0, 1, 1,
         dec_bo, 0, y, DM, 1.0f, 0, 0);
    layernorm_k<<<M, 128>>>(gH, gH);      // gH = h

    // ---------- stage 2: encoder-decoder attention (K,V from z, Q from h) ----------
    gemm(z, enc_Wk, gK, M, KD, DM, KD, 0, 0, (long long)DM * KD, 0, sKh, 0, HH, 1,
         enc_bk, KD, nullptr, 0, 1.0f, 0, 0);
    gemm(z, enc_Wv, gV, M, VD, DM, VD, 0, 0, (long long)DM * VD, 0, sKh, 0, HH, 1,
         enc_bv, VD, nullptr, 0, 1.0f, 0, 0);
    gemm(gH, enc_Wq, gQ, M, KD, DM, KD, 0, 0, (long long)DM * KD, 0, sKh, 0, HH, 1,
         enc_bq, KD, nullptr, 0, 1.0f, 0, 0);
    gemm(gQ, gK, gAtt, SSQ, SSQ, KD, SSQ, sKh, sKn, sKh, sKn, sAh, sAn, HH, NB,
         nullptr, 0, nullptr, 0, inv_scale, 1, 0);
    attn_post_k<<<dim3(SSQ, NB, HH), 256>>>(gAtt, genc, 0, 0.5f);
    gemm(gAtt, gV, gCtx, SSQ, VD, SSQ, DM, sAh, sAn, sKh, sKn, (long long)VD, (long long)SSQ * DM,
         HH, NB, nullptr, 0, nullptr, 0, 1.0f, 0, 0);
    gemm(gCtx, enc_Wo, gH2, M, DM, DM, DM, 0, 0, 0, 0, 0, 0, 1, 1,
         enc_bo, 0, gH, DM, 1.0f, 0, 0);
    layernorm_k<<<M, 128>>>(gH2, gH2);    // gH2 = h2

    // ---------- stage 3: MLP ----------
    gemm(gH2, fc_W1, gT, M, FCD, DM, FCD, 0, 0, 0, 0, 0, 0, 1, 1,
         fc_b1, 0, nullptr, 0, 1.0f, 0, 1);                 // relu
    gemm(gT, fc_W2, gH, M, DM, FCD, DM, 0, 0, 0, 0, 0, 0, 1, 1,
         fc_b2, 0, gH2, DM, 1.0f, 0, 0);                    // + residual h2
    layernorm_k<<<M, 128>>>(gH, out);
}

// round 10
// speedup vs baseline: 2.1772x; 2.1772x over previous
#include <cuda_runtime.h>
#include <math_constants.h>
#include <cstdint>
#include <cstddef>

// Problem constants
#define HH 8
#define KD 64
#define VD 64
#define KNN 128
#define DM 512
#define FCD 2048
#define NB 4
#define SSQ 1024
#define EPS 1e-5f

// ---------------- scratch (single __device__ array, no allocations) ----------------
constexpr size_t OFF_GDEC = 0;
constexpr size_t OFF_GENC = OFF_GDEC + (size_t)SSQ * SSQ;
constexpr size_t OFF_K    = OFF_GENC + (size_t)SSQ * SSQ;
constexpr size_t OFF_V    = OFF_K   + (size_t)HH * NB * SSQ * KD;
constexpr size_t OFF_Q    = OFF_V   + (size_t)HH * NB * SSQ * VD;
constexpr size_t OFF_CTX  = OFF_Q   + (size_t)HH * NB * SSQ * KD;
constexpr size_t OFF_H    = OFF_CTX + (size_t)NB * SSQ * DM;
constexpr size_t OFF_H2   = OFF_H   + (size_t)NB * SSQ * DM;
constexpr size_t OFF_T    = OFF_H2  + (size_t)NB * SSQ * DM;
constexpr size_t OFF_ATT  = OFF_T   + (size_t)NB * SSQ * FCD;
constexpr size_t SCRATCH_TOTAL = OFF_ATT + (size_t)HH * NB * SSQ * SSQ;

__device__ float g_scratch[SCRATCH_TOTAL];

// ---------------- TF32 / mma / ldmatrix helpers ----------------
__device__ __forceinline__ uint32_t f2tf32(float f) {
    uint32_t o;
    asm("cvt.rna.tf32.f32 %0, %1;" : "=r"(o) : "f"(f));
    return o;
}

__device__ __forceinline__ void mma_tf32v(float c[4],
                                          uint32_t a0, uint32_t a1, uint32_t a2, uint32_t a3,
                                          uint32_t b0, uint32_t b1)
{
    asm volatile(
        "mma.sync.aligned.m16n8k8.row.col.f32.tf32.tf32.f32 "
        "{%0,%1,%2,%3}, {%4,%5,%6,%7}, {%8,%9}, {%0,%1,%2,%3};"
        : "+f"(c[0]), "+f"(c[1]), "+f"(c[2]), "+f"(c[3])
        : "r"(a0), "r"(a1), "r"(a2), "r"(a3),
          "r"(b0), "r"(b1));
}

__device__ __forceinline__ void ldsm4(uint32_t& d0, uint32_t& d1, uint32_t& d2, uint32_t& d3,
                                      uint32_t addr)
{
    asm volatile("ldmatrix.sync.aligned.m8n8.x4.shared.b16 {%0,%1,%2,%3}, [%4];"
                 : "=r"(d0), "=r"(d1), "=r"(d2), "=r"(d3) : "r"(addr));
}

// ---------------- batched TF32 tensor-core GEMM, SW128-swizzled smem + ldmatrix --------
// C = alpha*A@B(^T) [+bias][relu][+resid]
// Block tile 128(M) x 64(N), K-tile 32, 256 threads = 8 warps (4x2),
// warp tile 32x32 = 2x4 m16n8k8 fragments, double-buffered smem.
// Smem tiles: A [128 rows m][8 chunks of 16B], B [64 rows n][8 chunks], row pitch 128B,
// chunk index XOR-swizzled by (row&7) -> conflict-free STS.128 and ldmatrix.
// Requirements: M % 128 == 0, Nc % 64 == 0, Kc % 32 == 0 (true for all calls).
__global__ __launch_bounds__(256) void gemm_k(
    const float* __restrict__ A, const float* __restrict__ B, float* __restrict__ C,
    int Nc, int Kc, int ldc,
    long long sAo, long long sAi, long long sBo, long long sBi,
    long long sCo, long long sCi, int Bi,
    const float* __restrict__ bias, long long sBias,
    const float* __restrict__ resid, int ldr,
    float alpha, int transB, int relu)
{
    __shared__ uint32_t As[2][4096];   // 128 rows * 32 words (128B) per tile
    __shared__ uint32_t Bs[2][2048];   // 64 rows * 32 words

    int z = blockIdx.z;
    int zo = z / Bi, zi = z - zo * Bi;
    A += (size_t)zo * sAo + (size_t)zi * sAi;
    B += (size_t)zo * sBo + (size_t)zi * sBi;
    C += (size_t)zo * sCo + (size_t)zi * sCi;
    const float* biasp = bias ? (bias + (size_t)zo * sBias) : nullptr;

    int bn0 = blockIdx.x * 64;
    int bm0 = blockIdx.y * 128;
    int t = threadIdx.x;
    int lane = t & 31, w = t >> 5;
    int wm = w >> 1, wn = w & 1;          // 4 x 2 warp grid
    int gid = lane >> 2, tg = lane & 3;

    // ---- loader mappings ----
    // A: 4 float4 per thread; idx = t + i*256 in [0,1024): row = idx>>3, kq = idx&7
    int a_row[4], a_kq[4], aSt[4];
    #pragma unroll
    for (int i = 0; i < 4; i++) {
        int idx = t + i * 256;
        a_row[i] = idx >> 3; a_kq[i] = idx & 7;
        aSt[i] = a_row[i] * 32 + ((a_kq[i] ^ (a_row[i] & 7)) << 2);
    }
    // B trans ([n][k] global): 2 float4; idx in [0,512): row n = idx>>3, kq = idx&7
    int bt_row[2], bt_kq[2], btSt[2];
    #pragma unroll
    for (int i = 0; i < 2; i++) {
        int idx = t + i * 256;
        bt_row[i] = idx >> 3; bt_kq[i] = idx & 7;
        btSt[i] = bt_row[i] * 32 + ((bt_kq[i] ^ (bt_row[i] & 7)) << 2);
    }
    // B non-trans ([k][n] global -> smem [n][k]): 2 groups; idx in [0,512):
    // n = idx&63, kseg = idx>>6 (4 k per group, gathered as 4 coalesced LDG.32)
    int bn_n[2], bn_ks[2], bnSt[2];
    #pragma unroll
    for (int i = 0; i < 2; i++) {
        int idx = t + i * 256;
        bn_n[i] = idx & 63; bn_ks[i] = idx >> 6;
        bnSt[i] = bn_n[i] * 32 + ((bn_ks[i] ^ (bn_n[i] & 7)) << 2);
    }

    // ---- fragment-load (ldmatrix) lane constants ----
    int r8 = lane & 7;
    int im = lane >> 3;                    // matrix index 0..3
    // A: matrices (i&1 -> +8 rows), (i>>1 -> chunk hi)
    int rowA0 = wm * 32 + r8 + 8 * (im & 1);      // mi=0 ; mi=1 adds 16
    int c1A = im >> 1;
    // B: matrix pairs: (i>>1 -> +8 rows), (i&1 -> chunk hi); p adds 16 rows
    int rowB0 = wn * 32 + r8 + 8 * (im >> 1);     // p=0 ; p=1 adds 16
    int c1B = im & 1;

    uint32_t sA[2], sB[2];
    sA[0] = (uint32_t)__cvta_generic_to_shared(&As[0][0]);
    sA[1] = (uint32_t)__cvta_generic_to_shared(&As[1][0]);
    sB[0] = (uint32_t)__cvta_generic_to_shared(&Bs[0][0]);
    sB[1] = (uint32_t)__cvta_generic_to_shared(&Bs[1][0]);

    float acc[2][4][4] = {};

    // ---- tile fetch/store helpers ----
    float4 pa[4]; float4 pbt[2]; float pbn[2][4];

    auto fetch_tile = [&](int k0) {
        #pragma unroll
        for (int i = 0; i < 4; i++)
            pa[i] = *(const float4*)&A[(size_t)(bm0 + a_row[i]) * Kc + k0 + a_kq[i] * 4];
        if (transB) {
            #pragma unroll
            for (int i = 0; i < 2; i++)
                pbt[i] = *(const float4*)&B[(size_t)(bn0 + bt_row[i]) * Kc + k0 + bt_kq[i] * 4];
        } else {
            #pragma unroll
            for (int i = 0; i < 2; i++)
                #pragma unroll
                for (int j = 0; j < 4; j++)
                    pbn[i][j] = B[(size_t)(k0 + bn_ks[i] * 4 + j) * Nc + bn0 + bn_n[i]];
        }
    };
    auto store_tile = [&](int buf) {
        #pragma unroll
        for (int i = 0; i < 4; i++) {
            uint4 u;
            u.x = f2tf32(pa[i].x); u.y = f2tf32(pa[i].y);
            u.z = f2tf32(pa[i].z); u.w = f2tf32(pa[i].w);
            *(uint4*)&As[buf][aSt[i]] = u;
        }
        if (transB) {
            #pragma unroll
            for (int i = 0; i < 2; i++) {
                uint4 u;
                u.x = f2tf32(pbt[i].x); u.y = f2tf32(pbt[i].y);
                u.z = f2tf32(pbt[i].z); u.w = f2tf32(pbt[i].w);
                *(uint4*)&Bs[buf][btSt[i]] = u;
            }
        } else {
            #pragma unroll
            for (int i = 0; i < 2; i++) {
                uint4 u;
                u.x = f2tf32(pbn[i][0]); u.y = f2tf32(pbn[i][1]);
                u.z = f2tf32(pbn[i][2]); u.w = f2tf32(pbn[i][3]);
                *(uint4*)&Bs[buf][bnSt[i]] = u;
            }
        }
    };

    // ---- prologue ----
    fetch_tile(0);
    store_tile(0);
    __syncthreads();

    int nT = Kc >> 5;
    int cur = 0;
    for (int tt = 0; tt < nT; tt++) {
        bool has = (tt + 1) < nT;
        if (has) fetch_tile((tt + 1) << 5);

        uint32_t baseA = sA[cur], baseB = sB[cur];
        #pragma unroll
        for (int ks = 0; ks < 4; ks++) {
            int ca = ((2 * ks + c1A) ^ r8) << 4;   // byte offset of swizzled chunk
            int cb = ((2 * ks + c1B) ^ r8) << 4;
            uint32_t af0[4], af1[4], bq0[4], bq1[4];
            ldsm4(af0[0], af0[1], af0[2], af0[3], baseA + (uint32_t)(rowA0 * 128 + ca));
            ldsm4(af1[0], af1[1], af1[2], af1[3], baseA + (uint32_t)((rowA0 + 16) * 128 + ca));
            ldsm4(bq0[0], bq0[1], bq0[2], bq0[3], baseB + (uint32_t)(rowB0 * 128 + cb));
            ldsm4(bq1[0], bq1[1], bq1[2], bq1[3], baseB + (uint32_t)((rowB0 + 16) * 128 + cb));
            mma_tf32v(acc[0][0], af0[0], af0[1], af0[2], af0[3], bq0[0], bq0[1]);
            mma_tf32v(acc[0][1], af0[0], af0[1], af0[2], af0[3], bq0[2], bq0[3]);
            mma_tf32v(acc[0][2], af0[0], af0[1], af0[2], af0[3], bq1[0], bq1[1]);
            mma_tf32v(acc[0][3], af0[0], af0[1], af0[2], af0[3], bq1[2], bq1[3]);
            mma_tf32v(acc[1][0], af1[0], af1[1], af1[2], af1[3], bq0[0], bq0[1]);
            mma_tf32v(acc[1][1], af1[0], af1[1], af1[2], af1[3], bq0[2], bq0[3]);
            mma_tf32v(acc[1][2], af1[0], af1[1], af1[2], af1[3], bq1[0], bq1[1]);
            mma_tf32v(acc[1][3], af1[0], af1[1], af1[2], af1[3], bq1[2], bq1[3]);
        }

        if (has) {
            int nxt = cur ^ 1;
            store_tile(nxt);
            __syncthreads();
            cur = nxt;
        }
    }

    // ---- epilogue ----
    // C fragment layout: c0:(g,2tg) c1:(g,2tg+1) c2:(g+8,2tg) c3:(g+8,2tg+1)
    int mb = wm * 32, nb = wn * 32;
    #pragma unroll
    for (int mi = 0; mi < 2; mi++) {
        int r0 = bm0 + mb + mi * 16 + gid;
        #pragma unroll
        for (int nj = 0; nj < 4; nj++) {
            int cc = bn0 + nb + nj * 8 + 2 * tg;
            float b0 = 0.f, b1 = 0.f;
            if (biasp) { b0 = biasp[cc]; b1 = biasp[cc + 1]; }
            #pragma unroll
            for (int half = 0; half < 2; half++) {
                int row = r0 + half * 8;
                float vx = acc[mi][nj][half * 2 + 0] * alpha + b0;
                float vy = acc[mi][nj][half * 2 + 1] * alpha + b1;
                if (relu) { vx = fmaxf(vx, 0.f); vy = fmaxf(vy, 0.f); }
                if (resid) {
                    float2 r = *(const float2*)&resid[(size_t)row * ldr + cc];
                    vx += r.x; vy += r.y;
                }
                float2 o; o.x = vx; o.y = vy;
                *(float2*)&C[(size_t)row * ldc + cc] = o;
            }
        }
    }
}

// ---------------- row softmax (graph preprocessing), rows of length SSQ ----------------
__global__ __launch_bounds__(256) void row_softmax_k(const float* __restrict__ in,
                                                     float* __restrict__ out)
{
    __shared__ float sh[8];
    int row = blockIdx.x;
    int t = threadIdx.x;
    int lane = t & 31, w = t >> 5;
    const float* rin = in + (size_t)row * SSQ;
    float* rout = out + (size_t)row * SSQ;

    float v[4];
    #pragma unroll
    for (int i = 0; i < 4; i++) v[i] = rin[t + i * 256];

    float m = fmaxf(fmaxf(v[0], v[1]), fmaxf(v[2], v[3]));
    #pragma unroll
    for (int o = 16; o; o >>= 1) m = fmaxf(m, __shfl_xor_sync(0xffffffffu, m, o));
    if (lane == 0) sh[w] = m;
    __syncthreads();
    m = sh[0];
    #pragma unroll
    for (int i = 1; i < 8; i++) m = fmaxf(m, sh[i]);
    __syncthreads();

    float e[4]; float s = 0.f;
    #pragma unroll
    for (int i = 0; i < 4; i++) { e[i] = expf(v[i] - m); s += e[i]; }
    #pragma unroll
    for (int o = 16; o; o >>= 1) s += __shfl_xor_sync(0xffffffffu, s, o);
    if (lane == 0) sh[w] = s;
    __syncthreads();
    s = 0.f;
    #pragma unroll
    for (int i = 0; i < 8; i++) s += sh[i];
    float inv = 1.0f / s;
    #pragma unroll
    for (int i = 0; i < 4; i++) rout[t + i * 256] = e[i] * inv;
}

// ---------------- fused: causal mask + exact top-KNN threshold + softmax + graph blend ----------------
__device__ __forceinline__ unsigned f2key(float f) {
    unsigned u = __float_as_uint(f);
    return (u & 0x80000000u) ? ~u : (u | 0x80000000u);
}

__global__ __launch_bounds__(256) void attn_post_k(float* __restrict__ att,
                                                   const float* __restrict__ graph,
                                                   int masked, float gw)
{
    __shared__ float sredf[8];
    __shared__ unsigned scount[2][8];

    int q = blockIdx.x, n = blockIdx.y, h = blockIdx.z;
    float* row = att + (((size_t)(h * NB + n)) * SSQ + q) * SSQ;
    const float* grow = graph + (size_t)q * SSQ;
    int L = masked ? (q + 1) : SSQ;

    int t = threadIdx.x;
    int lane = t & 31, w = t >> 5;

    float v[4]; unsigned key[4]; bool valid[4];
    #pragma unroll
    for (int i = 0; i < 4; i++) {
        int idx = t + i * 256;
        valid[i] = idx < L;
        v[i] = valid[i] ? row[idx] : -CUDART_INF_F;
        key[i] = valid[i] ? f2key(v[i]) : 0u;
    }

    unsigned threshKey = 0;
    if (L > KNN) {
        unsigned lo = 0u, hi = 0xFFFFFFFFu;
        unsigned it = 0;
        while (lo < hi) {
            unsigned mid = (unsigned)((((unsigned long long)lo + (unsigned long long)hi + 1ull)) >> 1);
            unsigned c = 0;
            #pragma unroll
            for (int i = 0; i < 4; i++) c += (key[i] >= mid) ? 1u : 0u;
            #pragma unroll
            for (int o = 16; o; o >>= 1) c += __shfl_xor_sync(0xffffffffu, c, o);
            unsigned* sc = scount[it & 1];
            if (lane == 0) sc[w] = c;
            __syncthreads();
            unsigned cnt = 0;
            #pragma unroll
            for (int i = 0; i < 8; i++) cnt += sc[i];
            if (cnt >= KNN) lo = mid; else hi = mid - 1u;
            it++;
        }
        threshKey = lo;
    }

    bool kept[4];
    #pragma unroll
    for (int i = 0; i < 4; i++)
        kept[i] = valid[i] && (L <= KNN || key[i] >= threshKey);

    float m = -CUDART_INF_F;
    #pragma unroll
    for (int i = 0; i < 4; i++) if (kept[i]) m = fmaxf(m, v[i]);
    #pragma unroll
    for (int o = 16; o; o >>= 1) m = fmaxf(m, __shfl_xor_sync(0xffffffffu, m, o));
    __syncthreads();   // protect sredf reuse vs earlier scount reads
    if (lane == 0) sredf[w] = m;
    __syncthreads();
    m = sredf[0];
    #pragma unroll
    for (int i = 1; i < 8; i++) m = fmaxf(m, sredf[i]);
    __syncthreads();

    float e[4]; float s = 0.f;
    #pragma unroll
    for (int i = 0; i < 4; i++) {
        e[i] = kept[i] ? expf(v[i] - m) : 0.f;
        s += e[i];
    }
    #pragma unroll
    for (int o = 16; o; o >>= 1) s += __shfl_xor_sync(0xffffffffu, s, o);
    if (lane == 0) sredf[w] = s;
    __syncthreads();
    s = 0.f;
    #pragma unroll
    for (int i = 0; i < 8; i++) s += sredf[i];
    float inv = 1.0f / s;

    float og = 1.0f - gw;
    #pragma unroll
    for (int i = 0; i < 4; i++) {
        int idx = t + i * 256;
        row[idx] = gw * grow[idx] + og * (e[i] * inv);
    }
}

// ---------------- LayerNorm over rows of DM=512 (elementwise_affine=False) ----------------
__global__ __launch_bounds__(128) void layernorm_k(const float* __restrict__ in,
                                                   float* __restrict__ out)
{
    __shared__ float sh[4];
    int row = blockIdx.x;
    int t = threadIdx.x;
    int lane = t & 31, w = t >> 5;
    const float* rin = in + (size_t)row * DM;
    float* rout = out + (size_t)row * DM;

    float v[4];
    #pragma unroll
    for (int i = 0; i < 4; i++) v[i] = rin[t + i * 128];

    float s = v[0] + v[1] + v[2] + v[3];
    #pragma unroll
    for (int o = 16; o; o >>= 1) s += __shfl_xor_sync(0xffffffffu, s, o);
    if (lane == 0) sh[w] = s;
    __syncthreads();
    s = sh[0] + sh[1] + sh[2] + sh[3];
    float mean = s * (1.0f / DM);
    __syncthreads();

    float sq = 0.f;
    #pragma unroll
    for (int i = 0; i < 4; i++) { float d = v[i] - mean; sq += d * d; }
    #pragma unroll
    for (int o = 16; o; o >>= 1) sq += __shfl_xor_sync(0xffffffffu, sq, o);
    if (lane == 0) sh[w] = sq;
    __syncthreads();
    sq = sh[0] + sh[1] + sh[2] + sh[3];
    float var = sq * (1.0f / DM);
    float inv = rsqrtf(var + EPS);

    #pragma unroll
    for (int i = 0; i < 4; i++) rout[t + i * 128] = (v[i] - mean) * inv;
}

// ---------------- host-side helpers ----------------
static inline void gemm(const float* A, const float* B, float* C,
                        int M, int Nc, int Kc, int ldc,
                        long long sAo, long long sAi, long long sBo, long long sBi,
                        long long sCo, long long sCi, int Bo, int Bi,
                        const float* bias, long long sBias,
                        const float* resid, int ldr,
                        float alpha, int transB, int relu)
{
    dim3 grid(Nc / 64, M / 128, Bo * Bi), block(256);
    gemm_k<<<grid, block>>>(A, B, C, Nc, Kc, ldc, sAo, sAi, sBo, sBi, sCo, sCi, Bi,
                            bias, sBias, resid, ldr, alpha, transB, relu);
}

extern "C" void kernel_launch(void* const* d_in, const int* in_sizes, int n_in,
                              void* d_out, int out_size)
{
    (void)in_sizes; (void)n_in; (void)out_size;
    const float* z        = (const float*)d_in[0];
    const float* y        = (const float*)d_in[1];
    const float* graphDec = (const float*)d_in[2];
    const float* graphEnc = (const float*)d_in[3];
    const float* dec_Wk   = (const float*)d_in[4];
    const float* dec_bk   = (const float*)d_in[5];
    const float* dec_Wv   = (const float*)d_in[6];
    const float* dec_bv   = (const float*)d_in[7];
    const float* dec_Wo   = (const float*)d_in[8];
    const float* dec_bo   = (const float*)d_in[9];
    const float* enc_Wk   = (const float*)d_in[10];
    const float* enc_bk   = (const float*)d_in[11];
    const float* enc_Wq   = (const float*)d_in[12];
    const float* enc_bq   = (const float*)d_in[13];
    const float* enc_Wv   = (const float*)d_in[14];
    const float* enc_bv   = (const float*)d_in[15];
    const float* enc_Wo   = (const float*)d_in[16];
    const float* enc_bo   = (const float*)d_in[17];
    const float* fc_W1    = (const float*)d_in[18];
    const float* fc_b1    = (const float*)d_in[19];
    const float* fc_W2    = (const float*)d_in[20];
    const float* fc_b2    = (const float*)d_in[21];
    float* out = (float*)d_out;

    float* sc = nullptr;
    cudaGetSymbolAddress((void**)&sc, g_scratch);
    float* gdec = sc + OFF_GDEC;
    float* genc = sc + OFF_GENC;
    float* gK   = sc + OFF_K;
    float* gV   = sc + OFF_V;
    float* gQ   = sc + OFF_Q;
    float* gCtx = sc + OFF_CTX;
    float* gH   = sc + OFF_H;
    float* gH2  = sc + OFF_H2;
    float* gT   = sc + OFF_T;
    float* gAtt = sc + OFF_ATT;

    const int M = NB * SSQ;               // 4096
    const long long sKh = (long long)NB * SSQ * KD;  // per-head stride in K/V/Q
    const long long sKn = (long long)SSQ * KD;       // per-batch stride
    const long long sAh = (long long)NB * SSQ * SSQ; // att per-head
    const long long sAn = (long long)SSQ * SSQ;      // att per-batch
    const float inv_scale = 0.125f;       // 1/sqrt(64)

    // 0) graph row-softmax
    row_softmax_k<<<SSQ, 256>>>(graphDec, gdec);
    row_softmax_k<<<SSQ, 256>>>(graphEnc, genc);

    // ---------- stage 1: masked decoder self-attention on y ----------
    gemm(y, dec_Wk, gK, M, KD, DM, KD, 0, 0, (long long)DM * KD, 0, sKh, 0, HH, 1,
         dec_bk, KD, nullptr, 0, 1.0f, 0, 0);
    gemm(y, dec_Wv, gV, M, VD, DM, VD, 0, 0, (long long)DM * VD, 0, sKh, 0, HH, 1,
         dec_bv, VD, nullptr, 0, 1.0f, 0, 0);
    gemm(gK, gK, gAtt, SSQ, SSQ, KD, SSQ, sKh, sKn, sKh, sKn, sAh, sAn, HH, NB,
         nullptr, 0, nullptr, 0, inv_scale, 1, 0);
    attn_post_k<<<dim3(SSQ, NB, HH), 256>>>(gAtt, gdec, 1, 0.5f);
    gemm(gAtt, gV, gCtx, SSQ, VD, SSQ, DM, sAh, sAn, sKh, sKn, (long long)VD, (long long)SSQ * DM,
         HH, NB, nullptr, 0, nullptr, 0, 1.0f, 0, 0);
    gemm(gCtx, dec_Wo, gH, M, DM, DM, DM, 0, 0, 0, 0, 0, 0, 1, 1,
         dec_bo, 0, y, DM, 1.0f, 0, 0);
    layernorm_k<<<M, 128>>>(gH, gH);      // gH = h

    // ---------- stage 2: encoder-decoder attention (K,V from z, Q from h) ----------
    gemm(z, enc_Wk, gK, M, KD, DM, KD, 0, 0, (long long)DM * KD, 0, sKh, 0, HH, 1,
         enc_bk, KD, nullptr, 0, 1.0f, 0, 0);
    gemm(z, enc_Wv, gV, M, VD, DM, VD, 0, 0, (long long)DM * VD, 0, sKh, 0, HH, 1,
         enc_bv, VD, nullptr, 0, 1.0f, 0, 0);
    gemm(gH, enc_Wq, gQ, M, KD, DM, KD, 0, 0, (long long)DM * KD, 0, sKh, 0, HH, 1,
         enc_bq, KD, nullptr, 0, 1.0f, 0, 0);
    gemm(gQ, gK, gAtt, SSQ, SSQ, KD, SSQ, sKh, sKn, sKh, sKn, sAh, sAn, HH, NB,
         nullptr, 0, nullptr, 0, inv_scale, 1, 0);
    attn_post_k<<<dim3(SSQ, NB, HH), 256>>>(gAtt, genc, 0, 0.5f);
    gemm(gAtt, gV, gCtx, SSQ, VD, SSQ, DM, sAh, sAn, sKh, sKn, (long long)VD, (long long)SSQ * DM,
         HH, NB, nullptr, 0, nullptr, 0, 1.0f, 0, 0);
    gemm(gCtx, enc_Wo, gH2, M, DM, DM, DM, 0, 0, 0, 0, 0, 0, 1, 1,
         enc_bo, 0, gH, DM, 1.0f, 0, 0);
    layernorm_k<<<M, 128>>>(gH2, gH2);    // gH2 = h2

    // ---------- stage 3: MLP ----------
    gemm(gH2, fc_W1, gT, M, FCD, DM, FCD, 0, 0, 0, 0, 0, 0, 1, 1,
         fc_b1, 0, nullptr, 0, 1.0f, 0, 1);                 // relu
    gemm(gT, fc_W2, gH, M, DM, FCD, DM, 0, 0, 0, 0, 0, 0, 1, 1,
         fc_b2, 0, gH2, DM, 1.0f, 0, 0);                    // + residual h2
    layernorm_k<<<M, 128>>>(gH, out);
}

// round 11
// speedup vs baseline: 3.2163x; 1.4772x over previous
#include <cuda_runtime.h>
#include <math_constants.h>
#include <cstdint>
#include <cstddef>

// Problem constants
#define HH 8
#define KD 64
#define VD 64
#define KNN 128
#define DM 512
#define FCD 2048
#define NB 4
#define SSQ 1024
#define EPS 1e-5f

// ---------------- scratch (single __device__ array, no allocations) ----------------
constexpr size_t OFF_GDEC = 0;
constexpr size_t OFF_GENC = OFF_GDEC + (size_t)SSQ * SSQ;
constexpr size_t OFF_K    = OFF_GENC + (size_t)SSQ * SSQ;
constexpr size_t OFF_V    = OFF_K   + (size_t)HH * NB * SSQ * KD;
constexpr size_t OFF_Q    = OFF_V   + (size_t)HH * NB * SSQ * VD;
constexpr size_t OFF_CTX  = OFF_Q   + (size_t)HH * NB * SSQ * KD;
constexpr size_t OFF_H    = OFF_CTX + (size_t)NB * SSQ * DM;
constexpr size_t OFF_H2   = OFF_H   + (size_t)NB * SSQ * DM;
constexpr size_t OFF_T    = OFF_H2  + (size_t)NB * SSQ * DM;
constexpr size_t OFF_ATT  = OFF_T   + (size_t)NB * SSQ * FCD;
constexpr size_t SCRATCH_TOTAL = OFF_ATT + (size_t)HH * NB * SSQ * SSQ;

__device__ float g_scratch[SCRATCH_TOTAL];

// ---------------- TF32 / mma / ldmatrix helpers ----------------
__device__ __forceinline__ uint32_t f2tf32(float f) {
    uint32_t o;
    asm("cvt.rna.tf32.f32 %0, %1;" : "=r"(o) : "f"(f));
    return o;
}

__device__ __forceinline__ void mma_tf32v(float c[4],
                                          uint32_t a0, uint32_t a1, uint32_t a2, uint32_t a3,
                                          uint32_t b0, uint32_t b1)
{
    asm volatile(
        "mma.sync.aligned.m16n8k8.row.col.f32.tf32.tf32.f32 "
        "{%0,%1,%2,%3}, {%4,%5,%6,%7}, {%8,%9}, {%0,%1,%2,%3};"
        : "+f"(c[0]), "+f"(c[1]), "+f"(c[2]), "+f"(c[3])
        : "r"(a0), "r"(a1), "r"(a2), "r"(a3),
          "r"(b0), "r"(b1));
}

__device__ __forceinline__ void ldsm4(uint32_t& d0, uint32_t& d1, uint32_t& d2, uint32_t& d3,
                                      uint32_t addr)
{
    asm volatile("ldmatrix.sync.aligned.m8n8.x4.shared.b16 {%0,%1,%2,%3}, [%4];"
                 : "=r"(d0), "=r"(d1), "=r"(d2), "=r"(d3) : "r"(addr));
}

// ---------------- batched TF32 tensor-core GEMM, SW128-swizzled smem + ldmatrix --------
// C = alpha*A@B(^T) [+bias][relu][+resid]
// Block tile 128(M) x 64(N), K-tile 32, 256 threads = 8 warps (4x2),
// warp tile 32x32 = 2x4 m16n8k8 fragments, double-buffered smem.
// Smem tiles: A [128 rows m][8 chunks of 16B], B [64 rows n][8 chunks], row pitch 128B,
// chunk index XOR-swizzled by (row&7) -> conflict-free STS.128 and ldmatrix.
// Requirements: M % 128 == 0, Nc % 64 == 0, Kc % 32 == 0 (true for all calls).
__global__ __launch_bounds__(256) void gemm_k(
    const float* __restrict__ A, const float* __restrict__ B, float* __restrict__ C,
    int Nc, int Kc, int ldc,
    long long sAo, long long sAi, long long sBo, long long sBi,
    long long sCo, long long sCi, int Bi,
    const float* __restrict__ bias, long long sBias,
    const float* __restrict__ resid, int ldr,
    float alpha, int transB, int relu)
{
    __shared__ uint32_t As[2][4096];   // 128 rows * 32 words (128B) per tile
    __shared__ uint32_t Bs[2][2048];   // 64 rows * 32 words

    int z = blockIdx.z;
    int zo = z / Bi, zi = z - zo * Bi;
    A += (size_t)zo * sAo + (size_t)zi * sAi;
    B += (size_t)zo * sBo + (size_t)zi * sBi;
    C += (size_t)zo * sCo + (size_t)zi * sCi;
    const float* biasp = bias ? (bias + (size_t)zo * sBias) : nullptr;

    int bn0 = blockIdx.x * 64;
    int bm0 = blockIdx.y * 128;
    int t = threadIdx.x;
    int lane = t & 31, w = t >> 5;
    int wm = w >> 1, wn = w & 1;          // 4 x 2 warp grid
    int gid = lane >> 2, tg = lane & 3;

    // ---- loader mappings ----
    int a_row[4], aSt[4];
    #pragma unroll
    for (int i = 0; i < 4; i++) {
        int idx = t + i * 256;
        a_row[i] = idx >> 3; int kq = idx & 7;
        aSt[i] = a_row[i] * 32 + ((kq ^ (a_row[i] & 7)) << 2);
    }
    int bt_row[2], btSt[2];
    #pragma unroll
    for (int i = 0; i < 2; i++) {
        int idx = t + i * 256;
        bt_row[i] = idx >> 3; int kq = idx & 7;
        btSt[i] = bt_row[i] * 32 + ((kq ^ (bt_row[i] & 7)) << 2);
    }
    int bn_n[2], bn_ks[2], bnSt[2];
    #pragma unroll
    for (int i = 0; i < 2; i++) {
        int idx = t + i * 256;
        bn_n[i] = idx & 63; bn_ks[i] = idx >> 6;
        bnSt[i] = bn_n[i] * 32 + ((bn_ks[i] ^ (bn_n[i] & 7)) << 2);
    }

    // ---- auto-incrementing global fetch pointers ----
    const float4* paP[4];
    #pragma unroll
    for (int i = 0; i < 4; i++)
        paP[i] = (const float4*)(A + (size_t)(bm0 + a_row[i]) * Kc) + ((t + i * 256) & 7);
    const float4* pbtP[2];
    const float*  pbnP[2];
    if (transB) {
        #pragma unroll
        for (int i = 0; i < 2; i++)
            pbtP[i] = (const float4*)(B + (size_t)(bn0 + bt_row[i]) * Kc) + ((t + i * 256) & 7);
    } else {
        #pragma unroll
        for (int i = 0; i < 2; i++)
            pbnP[i] = B + (size_t)(bn_ks[i] * 4) * Nc + bn0 + bn_n[i];
    }
    int nc1 = Nc, nc2 = 2 * Nc, nc3 = 3 * Nc;
    long long bnStep = (long long)Nc * 32;

    // ---- fragment-load (ldmatrix) lane constants + precomputed smem offsets ----
    int r8 = lane & 7;
    int im = lane >> 3;
    int rowA0 = wm * 32 + r8 + 8 * (im & 1);
    int c1A = im >> 1;
    int rowB0 = wn * 32 + r8 + 8 * (im >> 1);
    int c1B = im & 1;

    uint32_t offA[4], offB[4];
    #pragma unroll
    for (int ks = 0; ks < 4; ks++) {
        offA[ks] = (uint32_t)(rowA0 * 128 + (((2 * ks + c1A) ^ r8) << 4));
        offB[ks] = (uint32_t)(rowB0 * 128 + (((2 * ks + c1B) ^ r8) << 4));
    }

    uint32_t sA[2], sB[2];
    sA[0] = (uint32_t)__cvta_generic_to_shared(&As[0][0]);
    sA[1] = (uint32_t)__cvta_generic_to_shared(&As[1][0]);
    sB[0] = (uint32_t)__cvta_generic_to_shared(&Bs[0][0]);
    sB[1] = (uint32_t)__cvta_generic_to_shared(&Bs[1][0]);

    float acc[2][4][4] = {};

    float4 pa[4]; float4 pbt[2]; float pbn[2][4];

    auto fetch_tile = [&]() {
        #pragma unroll
        for (int i = 0; i < 4; i++) { pa[i] = *paP[i]; paP[i] += 8; }
        if (transB) {
            #pragma unroll
            for (int i = 0; i < 2; i++) { pbt[i] = *pbtP[i]; pbtP[i] += 8; }
        } else {
            #pragma unroll
            for (int i = 0; i < 2; i++) {
                pbn[i][0] = pbnP[i][0];   pbn[i][1] = pbnP[i][nc1];
                pbn[i][2] = pbnP[i][nc2]; pbn[i][3] = pbnP[i][nc3];
                pbnP[i] += bnStep;
            }
        }
    };
    auto store_tile = [&](int buf) {
        #pragma unroll
        for (int i = 0; i < 4; i++) {
            uint4 u;
            u.x = f2tf32(pa[i].x); u.y = f2tf32(pa[i].y);
            u.z = f2tf32(pa[i].z); u.w = f2tf32(pa[i].w);
            *(uint4*)&As[buf][aSt[i]] = u;
        }
        if (transB) {
            #pragma unroll
            for (int i = 0; i < 2; i++) {
                uint4 u;
                u.x = f2tf32(pbt[i].x); u.y = f2tf32(pbt[i].y);
                u.z = f2tf32(pbt[i].z); u.w = f2tf32(pbt[i].w);
                *(uint4*)&Bs[buf][btSt[i]] = u;
            }
        } else {
            #pragma unroll
            for (int i = 0; i < 2; i++) {
                uint4 u;
                u.x = f2tf32(pbn[i][0]); u.y = f2tf32(pbn[i][1]);
                u.z = f2tf32(pbn[i][2]); u.w = f2tf32(pbn[i][3]);
                *(uint4*)&Bs[buf][bnSt[i]] = u;
            }
        }
    };

    // ---- prologue ----
    fetch_tile();
    store_tile(0);
    __syncthreads();

    int nT = Kc >> 5;
    int cur = 0;
    for (int tt = 0; tt < nT; tt++) {
        bool has = (tt + 1) < nT;
        if (has) fetch_tile();

        uint32_t baseA = sA[cur], baseB = sB[cur];
        #pragma unroll
        for (int ks = 0; ks < 4; ks++) {
            uint32_t aAddr = baseA + offA[ks];
            uint32_t bAddr = baseB + offB[ks];
            uint32_t af0[4], af1[4], bq0[4], bq1[4];
            ldsm4(af0[0], af0[1], af0[2], af0[3], aAddr);
            ldsm4(af1[0], af1[1], af1[2], af1[3], aAddr + 2048);
            ldsm4(bq0[0], bq0[1], bq0[2], bq0[3], bAddr);
            ldsm4(bq1[0], bq1[1], bq1[2], bq1[3], bAddr + 2048);
            mma_tf32v(acc[0][0], af0[0], af0[1], af0[2], af0[3], bq0[0], bq0[1]);
            mma_tf32v(acc[0][1], af0[0], af0[1], af0[2], af0[3], bq0[2], bq0[3]);
            mma_tf32v(acc[0][2], af0[0], af0[1], af0[2], af0[3], bq1[0], bq1[1]);
            mma_tf32v(acc[0][3], af0[0], af0[1], af0[2], af0[3], bq1[2], bq1[3]);
            mma_tf32v(acc[1][0], af1[0], af1[1], af1[2], af1[3], bq0[0], bq0[1]);
            mma_tf32v(acc[1][1], af1[0], af1[1], af1[2], af1[3], bq0[2], bq0[3]);
            mma_tf32v(acc[1][2], af1[0], af1[1], af1[2], af1[3], bq1[0], bq1[1]);
            mma_tf32v(acc[1][3], af1[0], af1[1], af1[2], af1[3], bq1[2], bq1[3]);
        }

        if (has) {
            int nxt = cur ^ 1;
            store_tile(nxt);
            __syncthreads();
            cur = nxt;
        }
    }

    // ---- epilogue ----
    int mb = wm * 32, nb = wn * 32;
    #pragma unroll
    for (int mi = 0; mi < 2; mi++) {
        int r0 = bm0 + mb + mi * 16 + gid;
        #pragma unroll
        for (int nj = 0; nj < 4; nj++) {
            int cc = bn0 + nb + nj * 8 + 2 * tg;
            float b0 = 0.f, b1 = 0.f;
            if (biasp) { b0 = biasp[cc]; b1 = biasp[cc + 1]; }
            #pragma unroll
            for (int half = 0; half < 2; half++) {
                int row = r0 + half * 8;
                float vx = acc[mi][nj][half * 2 + 0] * alpha + b0;
                float vy = acc[mi][nj][half * 2 + 1] * alpha + b1;
                if (relu) { vx = fmaxf(vx, 0.f); vy = fmaxf(vy, 0.f); }
                if (resid) {
                    float2 r = *(const float2*)&resid[(size_t)row * ldr + cc];
                    vx += r.x; vy += r.y;
                }
                float2 o; o.x = vx; o.y = vy;
                *(float2*)&C[(size_t)row * ldc + cc] = o;
            }
        }
    }
}

// ---------------- row softmax (graph preprocessing), rows of length SSQ ----------------
__global__ __launch_bounds__(256) void row_softmax_k(const float* __restrict__ in,
                                                     float* __restrict__ out)
{
    __shared__ float sh[8];
    int row = blockIdx.x;
    int t = threadIdx.x;
    int lane = t & 31, w = t >> 5;
    const float* rin = in + (size_t)row * SSQ;
    float* rout = out + (size_t)row * SSQ;

    float4 v4 = *(const float4*)&rin[t * 4];
    float v[4] = {v4.x, v4.y, v4.z, v4.w};

    float m = fmaxf(fmaxf(v[0], v[1]), fmaxf(v[2], v[3]));
    #pragma unroll
    for (int o = 16; o; o >>= 1) m = fmaxf(m, __shfl_xor_sync(0xffffffffu, m, o));
    if (lane == 0) sh[w] = m;
    __syncthreads();
    m = sh[0];
    #pragma unroll
    for (int i = 1; i < 8; i++) m = fmaxf(m, sh[i]);
    __syncthreads();

    float e[4]; float s = 0.f;
    #pragma unroll
    for (int i = 0; i < 4; i++) { e[i] = expf(v[i] - m); s += e[i]; }
    #pragma unroll
    for (int o = 16; o; o >>= 1) s += __shfl_xor_sync(0xffffffffu, s, o);
    if (lane == 0) sh[w] = s;
    __syncthreads();
    s = 0.f;
    #pragma unroll
    for (int i = 0; i < 8; i++) s += sh[i];
    float inv = 1.0f / s;
    float4 o4;
    o4.x = e[0] * inv; o4.y = e[1] * inv; o4.z = e[2] * inv; o4.w = e[3] * inv;
    *(float4*)&rout[t * 4] = o4;
}

// ---------------- fused: causal mask + exact top-KNN threshold + softmax + graph blend ----------------
__device__ __forceinline__ unsigned f2key(float f) {
    unsigned u = __float_as_uint(f);
    return (u & 0x80000000u) ? ~u : (u | 0x80000000u);
}

__global__ __launch_bounds__(256) void attn_post_k(float* __restrict__ att,
                                                   const float* __restrict__ graph,
                                                   int masked, float gw)
{
    __shared__ float sredf[8];
    __shared__ unsigned scount[2][8];

    int q = blockIdx.x, n = blockIdx.y, h = blockIdx.z;
    float* row = att + (((size_t)(h * NB + n)) * SSQ + q) * SSQ;
    const float* grow = graph + (size_t)q * SSQ;
    int L = masked ? (q + 1) : SSQ;

    int t = threadIdx.x;
    int lane = t & 31, w = t >> 5;
    int base = t * 4;

    float4 v4 = *(const float4*)&row[base];
    float v[4] = {v4.x, v4.y, v4.z, v4.w};
    unsigned key[4]; bool valid[4];
    #pragma unroll
    for (int i = 0; i < 4; i++) {
        valid[i] = (base + i) < L;
        if (!valid[i]) v[i] = -CUDART_INF_F;
        key[i] = valid[i] ? f2key(v[i]) : 0u;
    }

    // ---- block max over valid (reused as search hi-bound AND softmax max) ----
    float m = fmaxf(fmaxf(v[0], v[1]), fmaxf(v[2], v[3]));   // -inf for invalid ok
    #pragma unroll
    for (int o = 16; o; o >>= 1) m = fmaxf(m, __shfl_xor_sync(0xffffffffu, m, o));
    if (lane == 0) sredf[w] = m;
    __syncthreads();
    m = sredf[0];
    #pragma unroll
    for (int i = 1; i < 8; i++) m = fmaxf(m, sredf[i]);
    __syncthreads();   // all sredf reads done before reuse below

    // ---- exact top-KNN threshold: binary search on sign-flipped bits, early exit ----
    unsigned threshKey = 0;
    if (L > KNN) {
        unsigned lo = 0u, hi = f2key(m);
        unsigned it = 0;
        while (lo < hi) {
            unsigned mid = (unsigned)((((unsigned long long)lo + (unsigned long long)hi + 1ull)) >> 1);
            unsigned c = 0;
            #pragma unroll
            for (int i = 0; i < 4; i++) c += (key[i] >= mid) ? 1u : 0u;
            c = __reduce_add_sync(0xffffffffu, c);
            unsigned* sc = scount[it & 1];
            if (lane == 0) sc[w] = c;
            __syncthreads();
            unsigned cnt = 0;
            #pragma unroll
            for (int i = 0; i < 8; i++) cnt += sc[i];
            if (cnt == KNN) { lo = mid; break; }   // exact: {key>=mid} == top-KNN set
            if (cnt > KNN) lo = mid; else hi = mid - 1u;
            it++;
        }
        threshKey = lo;
    }

    bool kept[4];
    #pragma unroll
    for (int i = 0; i < 4; i++)
        kept[i] = valid[i] && (L <= KNN || key[i] >= threshKey);

    // ---- softmax over kept (max = m) ----
    float e[4]; float s = 0.f;
    #pragma unroll
    for (int i = 0; i < 4; i++) {
        e[i] = kept[i] ? expf(v[i] - m) : 0.f;
        s += e[i];
    }
    #pragma unroll
    for (int o = 16; o; o >>= 1) s += __shfl_xor_sync(0xffffffffu, s, o);
    __syncthreads();   // protect sredf reuse (search path may skip barriers when L<=KNN)
    if (lane == 0) sredf[w] = s;
    __syncthreads();
    s = 0.f;
    #pragma unroll
    for (int i = 0; i < 8; i++) s += sredf[i];
    float inv = 1.0f / s;

    float og = 1.0f - gw;
    float4 g4 = *(const float4*)&grow[base];
    float gv[4] = {g4.x, g4.y, g4.z, g4.w};
    float4 o4;
    o4.x = gw * gv[0] + og * (e[0] * inv);
    o4.y = gw * gv[1] + og * (e[1] * inv);
    o4.z = gw * gv[2] + og * (e[2] * inv);
    o4.w = gw * gv[3] + og * (e[3] * inv);
    *(float4*)&row[base] = o4;
}

// ---------------- LayerNorm over rows of DM=512 (elementwise_affine=False) ----------------
__global__ __launch_bounds__(128) void layernorm_k(const float* __restrict__ in,
                                                   float* __restrict__ out)
{
    __shared__ float sh[4];
    int row = blockIdx.x;
    int t = threadIdx.x;
    int lane = t & 31, w = t >> 5;
    const float* rin = in + (size_t)row * DM;
    float* rout = out + (size_t)row * DM;

    float4 v4 = *(const float4*)&rin[t * 4];
    float v[4] = {v4.x, v4.y, v4.z, v4.w};

    float s = v[0] + v[1] + v[2] + v[3];
    #pragma unroll
    for (int o = 16; o; o >>= 1) s += __shfl_xor_sync(0xffffffffu, s, o);
    if (lane == 0) sh[w] = s;
    __syncthreads();
    s = sh[0] + sh[1] + sh[2] + sh[3];
    float mean = s * (1.0f / DM);
    __syncthreads();

    float sq = 0.f;
    #pragma unroll
    for (int i = 0; i < 4; i++) { float d = v[i] - mean; sq += d * d; }
    #pragma unroll
    for (int o = 16; o; o >>= 1) sq += __shfl_xor_sync(0xffffffffu, sq, o);
    if (lane == 0) sh[w] = sq;
    __syncthreads();
    sq = sh[0] + sh[1] + sh[2] + sh[3];
    float var = sq * (1.0f / DM);
    float inv = rsqrtf(var + EPS);

    float4 o4;
    o4.x = (v[0] - mean) * inv; o4.y = (v[1] - mean) * inv;
    o4.z = (v[2] - mean) * inv; o4.w = (v[3] - mean) * inv;
    *(float4*)&rout[t * 4] = o4;
}

// ---------------- host-side helpers ----------------
static inline void gemm(const float* A, const float* B, float* C,
                        int M, int Nc, int Kc, int ldc,
                        long long sAo, long long sAi, long long sBo, long long sBi,
                        long long sCo, long long sCi, int Bo, int Bi,
                        const float* bias, long long sBias,
                        const float* resid, int ldr,
                        float alpha, int transB, int relu)
{
    dim3 grid(Nc / 64, M / 128, Bo * Bi), block(256);
    gemm_k<<<grid, block>>>(A, B, C, Nc, Kc, ldc, sAo, sAi, sBo, sBi, sCo, sCi, Bi,
                            bias, sBias, resid, ldr, alpha, transB, relu);
}

extern "C" void kernel_launch(void* const* d_in, const int* in_sizes, int n_in,
                              void* d_out, int out_size)
{
    (void)in_sizes; (void)n_in; (void)out_size;
    const float* z        = (const float*)d_in[0];
    const float* y        = (const float*)d_in[1];
    const float* graphDec = (const float*)d_in[2];
    const float* graphEnc = (const float*)d_in[3];
    const float* dec_Wk   = (const float*)d_in[4];
    const float* dec_bk   = (const float*)d_in[5];
    const float* dec_Wv   = (const float*)d_in[6];
    const float* dec_bv   = (const float*)d_in[7];
    const float* dec_Wo   = (const float*)d_in[8];
    const float* dec_bo   = (const float*)d_in[9];
    const float* enc_Wk   = (const float*)d_in[10];
    const float* enc_bk   = (const float*)d_in[11];
    const float* enc_Wq   = (const float*)d_in[12];
    const float* enc_bq   = (const float*)d_in[13];
    const float* enc_Wv   = (const float*)d_in[14];
    const float* enc_bv   = (const float*)d_in[15];
    const float* enc_Wo   = (const float*)d_in[16];
    const float* enc_bo   = (const float*)d_in[17];
    const float* fc_W1    = (const float*)d_in[18];
    const float* fc_b1    = (const float*)d_in[19];
    const float* fc_W2    = (const float*)d_in[20];
    const float* fc_b2    = (const float*)d_in[21];
    float* out = (float*)d_out;

    float* sc = nullptr;
    cudaGetSymbolAddress((void**)&sc, g_scratch);
    float* gdec = sc + OFF_GDEC;
    float* genc = sc + OFF_GENC;
    float* gK   = sc + OFF_K;
    float* gV   = sc + OFF_V;
    float* gQ   = sc + OFF_Q;
    float* gCtx = sc + OFF_CTX;
    float* gH   = sc + OFF_H;
    float* gH2  = sc + OFF_H2;
    float* gT   = sc + OFF_T;
    float* gAtt = sc + OFF_ATT;

    const int M = NB * SSQ;               // 4096
    const long long sKh = (long long)NB * SSQ * KD;  // per-head stride in K/V/Q
    const long long sKn = (long long)SSQ * KD;       // per-batch stride
    const long long sAh = (long long)NB * SSQ * SSQ; // att per-head
    const long long sAn = (long long)SSQ * SSQ;      // att per-batch
    const float inv_scale = 0.125f;       // 1/sqrt(64)

    // 0) graph row-softmax
    row_softmax_k<<<SSQ, 256>>>(graphDec, gdec);
    row_softmax_k<<<SSQ, 256>>>(graphEnc, genc);

    // ---------- stage 1: masked decoder self-attention on y ----------
    gemm(y, dec_Wk, gK, M, KD, DM, KD, 0, 0, (long long)DM * KD, 0, sKh, 0, HH, 1,
         dec_bk, KD, nullptr, 0, 1.0f, 0, 0);
    gemm(y, dec_Wv, gV, M, VD, DM, VD, 0, 0, (long long)DM * VD, 0, sKh, 0, HH, 1,
         dec_bv, VD, nullptr, 0, 1.0f, 0, 0);
    gemm(gK, gK, gAtt, SSQ, SSQ, KD, SSQ, sKh, sKn, sKh, sKn, sAh, sAn, HH, NB,
         nullptr, 0, nullptr, 0, inv_scale, 1, 0);
    attn_post_k<<<dim3(SSQ, NB, HH), 256>>>(gAtt, gdec, 1, 0.5f);
    gemm(gAtt, gV, gCtx, SSQ, VD, SSQ, DM, sAh, sAn, sKh, sKn, (long long)VD, (long long)SSQ * DM,
         HH, NB, nullptr, 0, nullptr, 0, 1.0f, 0, 0);
    gemm(gCtx, dec_Wo, gH, M, DM, DM, DM, 0, 0, 0, 0, 0, 0, 1, 1,
         dec_bo, 0, y, DM, 1.0f, 0, 0);
    layernorm_k<<<M, 128>>>(gH, gH);      // gH = h

    // ---------- stage 2: encoder-decoder attention (K,V from z, Q from h) ----------
    gemm(z, enc_Wk, gK, M, KD, DM, KD, 0, 0, (long long)DM * KD, 0, sKh, 0, HH, 1,
         enc_bk, KD, nullptr, 0, 1.0f, 0, 0);
    gemm(z, enc_Wv, gV, M, VD, DM, VD, 0, 0, (long long)DM * VD, 0, sKh, 0, HH, 1,
         enc_bv, VD, nullptr, 0, 1.0f, 0, 0);
    gemm(gH, enc_Wq, gQ, M, KD, DM, KD, 0, 0, (long long)DM * KD, 0, sKh, 0, HH, 1,
         enc_bq, KD, nullptr, 0, 1.0f, 0, 0);
    gemm(gQ, gK, gAtt, SSQ, SSQ, KD, SSQ, sKh, sKn, sKh, sKn, sAh, sAn, HH, NB,
         nullptr, 0, nullptr, 0, inv_scale, 1, 0);
    attn_post_k<<<dim3(SSQ, NB, HH), 256>>>(gAtt, genc, 0, 0.5f);
    gemm(gAtt, gV, gCtx, SSQ, VD, SSQ, DM, sAh, sAn, sKh, sKn, (long long)VD, (long long)SSQ * DM,
         HH, NB, nullptr, 0, nullptr, 0, 1.0f, 0, 0);
    gemm(gCtx, enc_Wo, gH2, M, DM, DM, DM, 0, 0, 0, 0, 0, 0, 1, 1,
         enc_bo, 0, gH, DM, 1.0f, 0, 0);
    layernorm_k<<<M, 128>>>(gH2, gH2);    // gH2 = h2

    // ---------- stage 3: MLP ----------
    gemm(gH2, fc_W1, gT, M, FCD, DM, FCD, 0, 0, 0, 0, 0, 0, 1, 1,
         fc_b1, 0, nullptr, 0, 1.0f, 0, 1);                 // relu
    gemm(gT, fc_W2, gH, M, DM, FCD, DM, 0, 0, 0, 0, 0, 0, 1, 1,
         fc_b2, 0, gH2, DM, 1.0f, 0, 0);                    // + residual h2
    layernorm_k<<<M, 128>>>(gH, out);
}

// round 12
// speedup vs baseline: 3.9652x; 1.2329x over previous
#include <cuda_runtime.h>
#include <math_constants.h>
#include <cstdint>
#include <cstddef>

// Problem constants
#define HH 8
#define KD 64
#define VD 64
#define KNN 128
#define DM 512
#define FCD 2048
#define NB 4
#define SSQ 1024
#define EPS 1e-5f

// ---------------- scratch (single __device__ array, no allocations) ----------------
constexpr size_t OFF_GDEC = 0;
constexpr size_t OFF_GENC = OFF_GDEC + (size_t)SSQ * SSQ;
constexpr size_t OFF_K    = OFF_GENC + (size_t)SSQ * SSQ;
constexpr size_t OFF_V    = OFF_K   + (size_t)HH * NB * SSQ * KD;
constexpr size_t OFF_Q    = OFF_V   + (size_t)HH * NB * SSQ * VD;
constexpr size_t OFF_CTX  = OFF_Q   + (size_t)HH * NB * SSQ * KD;
constexpr size_t OFF_H    = OFF_CTX + (size_t)NB * SSQ * DM;
constexpr size_t OFF_H2   = OFF_H   + (size_t)NB * SSQ * DM;
constexpr size_t OFF_T    = OFF_H2  + (size_t)NB * SSQ * DM;
constexpr size_t OFF_ATT  = OFF_T   + (size_t)NB * SSQ * FCD;
constexpr size_t SCRATCH_TOTAL = OFF_ATT + (size_t)HH * NB * SSQ * SSQ;

__device__ float g_scratch[SCRATCH_TOTAL];

// ---------------- TF32 / mma / ldmatrix helpers ----------------
__device__ __forceinline__ uint32_t f2tf32(float f) {
    uint32_t o;
    asm("cvt.rna.tf32.f32 %0, %1;" : "=r"(o) : "f"(f));
    return o;
}

__device__ __forceinline__ void mma_tf32v(float c[4],
                                          uint32_t a0, uint32_t a1, uint32_t a2, uint32_t a3,
                                          uint32_t b0, uint32_t b1)
{
    asm volatile(
        "mma.sync.aligned.m16n8k8.row.col.f32.tf32.tf32.f32 "
        "{%0,%1,%2,%3}, {%4,%5,%6,%7}, {%8,%9}, {%0,%1,%2,%3};"
        : "+f"(c[0]), "+f"(c[1]), "+f"(c[2]), "+f"(c[3])
        : "r"(a0), "r"(a1), "r"(a2), "r"(a3),
          "r"(b0), "r"(b1));
}

__device__ __forceinline__ void ldsm4(uint32_t& d0, uint32_t& d1, uint32_t& d2, uint32_t& d3,
                                      uint32_t addr)
{
    asm volatile("ldmatrix.sync.aligned.m8n8.x4.shared.b16 {%0,%1,%2,%3}, [%4];"
                 : "=r"(d0), "=r"(d1), "=r"(d2), "=r"(d3) : "r"(addr));
}

// ---------------- batched TF32 tensor-core GEMM, SW128-swizzled smem + ldmatrix --------
// C = alpha*A@B(^T) [+bias][relu][+resid]
// Block tile 128(M) x 64(N), K-tile 32, 256 threads = 8 warps (4x2),
// warp tile 32x32 = 2x4 m16n8k8 fragments, double-buffered smem.
// causal=1: skip blocks entirely above the diagonal (bn0 >= bm0+128) — their
// outputs are never consumed by the masked attn_post.
__global__ __launch_bounds__(256) void gemm_k(
    const float* __restrict__ A, const float* __restrict__ B, float* __restrict__ C,
    int Nc, int Kc, int ldc,
    long long sAo, long long sAi, long long sBo, long long sBi,
    long long sCo, long long sCi, int Bi,
    const float* __restrict__ bias, long long sBias,
    const float* __restrict__ resid, int ldr,
    float alpha, int transB, int relu, int causal)
{
    __shared__ uint32_t As[2][4096];   // 128 rows * 32 words (128B) per tile
    __shared__ uint32_t Bs[2][2048];   // 64 rows * 32 words

    int bn0 = blockIdx.x * 64;
    int bm0 = blockIdx.y * 128;
    if (causal && bn0 >= bm0 + 128) return;

    int z = blockIdx.z;
    int zo = z / Bi, zi = z - zo * Bi;
    A += (size_t)zo * sAo + (size_t)zi * sAi;
    B += (size_t)zo * sBo + (size_t)zi * sBi;
    C += (size_t)zo * sCo + (size_t)zi * sCi;
    const float* biasp = bias ? (bias + (size_t)zo * sBias) : nullptr;

    int t = threadIdx.x;
    int lane = t & 31, w = t >> 5;
    int wm = w >> 1, wn = w & 1;          // 4 x 2 warp grid
    int gid = lane >> 2, tg = lane & 3;

    // ---- loader mappings ----
    int a_row[4], aSt[4];
    #pragma unroll
    for (int i = 0; i < 4; i++) {
        int idx = t + i * 256;
        a_row[i] = idx >> 3; int kq = idx & 7;
        aSt[i] = a_row[i] * 32 + ((kq ^ (a_row[i] & 7)) << 2);
    }
    int bt_row[2], btSt[2];
    #pragma unroll
    for (int i = 0; i < 2; i++) {
        int idx = t + i * 256;
        bt_row[i] = idx >> 3; int kq = idx & 7;
        btSt[i] = bt_row[i] * 32 + ((kq ^ (bt_row[i] & 7)) << 2);
    }
    int bn_n[2], bn_ks[2], bnSt[2];
    #pragma unroll
    for (int i = 0; i < 2; i++) {
        int idx = t + i * 256;
        bn_n[i] = idx & 63; bn_ks[i] = idx >> 6;
        bnSt[i] = bn_n[i] * 32 + ((bn_ks[i] ^ (bn_n[i] & 7)) << 2);
    }

    // ---- auto-incrementing global fetch pointers ----
    const float4* paP[4];
    #pragma unroll
    for (int i = 0; i < 4; i++)
        paP[i] = (const float4*)(A + (size_t)(bm0 + a_row[i]) * Kc) + ((t + i * 256) & 7);
    const float4* pbtP[2];
    const float*  pbnP[2];
    if (transB) {
        #pragma unroll
        for (int i = 0; i < 2; i++)
            pbtP[i] = (const float4*)(B + (size_t)(bn0 + bt_row[i]) * Kc) + ((t + i * 256) & 7);
    } else {
        #pragma unroll
        for (int i = 0; i < 2; i++)
            pbnP[i] = B + (size_t)(bn_ks[i] * 4) * Nc + bn0 + bn_n[i];
    }
    int nc1 = Nc, nc2 = 2 * Nc, nc3 = 3 * Nc;
    long long bnStep = (long long)Nc * 32;

    // ---- fragment-load (ldmatrix) lane constants + precomputed smem offsets ----
    int r8 = lane & 7;
    int im = lane >> 3;
    int rowA0 = wm * 32 + r8 + 8 * (im & 1);
    int c1A = im >> 1;
    int rowB0 = wn * 32 + r8 + 8 * (im >> 1);
    int c1B = im & 1;

    uint32_t offA[4], offB[4];
    #pragma unroll
    for (int ks = 0; ks < 4; ks++) {
        offA[ks] = (uint32_t)(rowA0 * 128 + (((2 * ks + c1A) ^ r8) << 4));
        offB[ks] = (uint32_t)(rowB0 * 128 + (((2 * ks + c1B) ^ r8) << 4));
    }

    uint32_t sA[2], sB[2];
    sA[0] = (uint32_t)__cvta_generic_to_shared(&As[0][0]);
    sA[1] = (uint32_t)__cvta_generic_to_shared(&As[1][0]);
    sB[0] = (uint32_t)__cvta_generic_to_shared(&Bs[0][0]);
    sB[1] = (uint32_t)__cvta_generic_to_shared(&Bs[1][0]);

    float acc[2][4][4] = {};

    float4 pa[4]; float4 pbt[2]; float pbn[2][4];

    auto fetch_tile = [&]() {
        #pragma unroll
        for (int i = 0; i < 4; i++) { pa[i] = *paP[i]; paP[i] += 8; }
        if (transB) {
            #pragma unroll
            for (int i = 0; i < 2; i++) { pbt[i] = *pbtP[i]; pbtP[i] += 8; }
        } else {
            #pragma unroll
            for (int i = 0; i < 2; i++) {
                pbn[i][0] = pbnP[i][0];   pbn[i][1] = pbnP[i][nc1];
                pbn[i][2] = pbnP[i][nc2]; pbn[i][3] = pbnP[i][nc3];
                pbnP[i] += bnStep;
            }
        }
    };
    auto store_tile = [&](int buf) {
        #pragma unroll
        for (int i = 0; i < 4; i++) {
            uint4 u;
            u.x = f2tf32(pa[i].x); u.y = f2tf32(pa[i].y);
            u.z = f2tf32(pa[i].z); u.w = f2tf32(pa[i].w);
            *(uint4*)&As[buf][aSt[i]] = u;
        }
        if (transB) {
            #pragma unroll
            for (int i = 0; i < 2; i++) {
                uint4 u;
                u.x = f2tf32(pbt[i].x); u.y = f2tf32(pbt[i].y);
                u.z = f2tf32(pbt[i].z); u.w = f2tf32(pbt[i].w);
                *(uint4*)&Bs[buf][btSt[i]] = u;
            }
        } else {
            #pragma unroll
            for (int i = 0; i < 2; i++) {
                uint4 u;
                u.x = f2tf32(pbn[i][0]); u.y = f2tf32(pbn[i][1]);
                u.z = f2tf32(pbn[i][2]); u.w = f2tf32(pbn[i][3]);
                *(uint4*)&Bs[buf][bnSt[i]] = u;
            }
        }
    };

    // ---- prologue ----
    fetch_tile();
    store_tile(0);
    __syncthreads();

    int nT = Kc >> 5;
    int cur = 0;
    for (int tt = 0; tt < nT; tt++) {
        bool has = (tt + 1) < nT;
        if (has) fetch_tile();

        uint32_t baseA = sA[cur], baseB = sB[cur];
        #pragma unroll
        for (int ks = 0; ks < 4; ks++) {
            uint32_t aAddr = baseA + offA[ks];
            uint32_t bAddr = baseB + offB[ks];
            uint32_t af0[4], af1[4], bq0[4], bq1[4];
            ldsm4(af0[0], af0[1], af0[2], af0[3], aAddr);
            ldsm4(af1[0], af1[1], af1[2], af1[3], aAddr + 2048);
            ldsm4(bq0[0], bq0[1], bq0[2], bq0[3], bAddr);
            ldsm4(bq1[0], bq1[1], bq1[2], bq1[3], bAddr + 2048);
            mma_tf32v(acc[0][0], af0[0], af0[1], af0[2], af0[3], bq0[0], bq0[1]);
            mma_tf32v(acc[0][1], af0[0], af0[1], af0[2], af0[3], bq0[2], bq0[3]);
            mma_tf32v(acc[0][2], af0[0], af0[1], af0[2], af0[3], bq1[0], bq1[1]);
            mma_tf32v(acc[0][3], af0[0], af0[1], af0[2], af0[3], bq1[2], bq1[3]);
            mma_tf32v(acc[1][0], af1[0], af1[1], af1[2], af1[3], bq0[0], bq0[1]);
            mma_tf32v(acc[1][1], af1[0], af1[1], af1[2], af1[3], bq0[2], bq0[3]);
            mma_tf32v(acc[1][2], af1[0], af1[1], af1[2], af1[3], bq1[0], bq1[1]);
            mma_tf32v(acc[1][3], af1[0], af1[1], af1[2], af1[3], bq1[2], bq1[3]);
        }

        if (has) {
            int nxt = cur ^ 1;
            store_tile(nxt);
            __syncthreads();
            cur = nxt;
        }
    }

    // ---- epilogue ----
    int mb = wm * 32, nb = wn * 32;
    #pragma unroll
    for (int mi = 0; mi < 2; mi++) {
        int r0 = bm0 + mb + mi * 16 + gid;
        #pragma unroll
        for (int nj = 0; nj < 4; nj++) {
            int cc = bn0 + nb + nj * 8 + 2 * tg;
            float b0 = 0.f, b1 = 0.f;
            if (biasp) { b0 = biasp[cc]; b1 = biasp[cc + 1]; }
            #pragma unroll
            for (int half = 0; half < 2; half++) {
                int row = r0 + half * 8;
                float vx = acc[mi][nj][half * 2 + 0] * alpha + b0;
                float vy = acc[mi][nj][half * 2 + 1] * alpha + b1;
                if (relu) { vx = fmaxf(vx, 0.f); vy = fmaxf(vy, 0.f); }
                if (resid) {
                    float2 r = *(const float2*)&resid[(size_t)row * ldr + cc];
                    vx += r.x; vy += r.y;
                }
                float2 o; o.x = vx; o.y = vy;
                *(float2*)&C[(size_t)row * ldc + cc] = o;
            }
        }
    }
}

// ---------------- row softmax (graph preprocessing), rows of length SSQ ----------------
__global__ __launch_bounds__(256) void row_softmax_k(const float* __restrict__ in,
                                                     float* __restrict__ out)
{
    __shared__ float sh[8];
    int row = blockIdx.x;
    int t = threadIdx.x;
    int lane = t & 31, w = t >> 5;
    const float* rin = in + (size_t)row * SSQ;
    float* rout = out + (size_t)row * SSQ;

    float4 v4 = *(const float4*)&rin[t * 4];
    float v[4] = {v4.x, v4.y, v4.z, v4.w};

    float m = fmaxf(fmaxf(v[0], v[1]), fmaxf(v[2], v[3]));
    #pragma unroll
    for (int o = 16; o; o >>= 1) m = fmaxf(m, __shfl_xor_sync(0xffffffffu, m, o));
    if (lane == 0) sh[w] = m;
    __syncthreads();
    m = sh[0];
    #pragma unroll
    for (int i = 1; i < 8; i++) m = fmaxf(m, sh[i]);
    __syncthreads();

    float e[4]; float s = 0.f;
    #pragma unroll
    for (int i = 0; i < 4; i++) { e[i] = expf(v[i] - m); s += e[i]; }
    #pragma unroll
    for (int o = 16; o; o >>= 1) s += __shfl_xor_sync(0xffffffffu, s, o);
    if (lane == 0) sh[w] = s;
    __syncthreads();
    s = 0.f;
    #pragma unroll
    for (int i = 0; i < 8; i++) s += sh[i];
    float inv = 1.0f / s;
    float4 o4;
    o4.x = e[0] * inv; o4.y = e[1] * inv; o4.z = e[2] * inv; o4.w = e[3] * inv;
    *(float4*)&rout[t * 4] = o4;
}

// ---------------- fused: causal mask + exact top-KNN + softmax + graph blend ----------
// One WARP per attention row: keys in 32 regs, REDUX reductions, zero barriers.
__device__ __forceinline__ unsigned f2key(float f) {
    unsigned u = __float_as_uint(f);
    return (u & 0x80000000u) ? ~u : (u | 0x80000000u);
}
__device__ __forceinline__ float key2f(unsigned k) {
    unsigned u = (k & 0x80000000u) ? (k & 0x7fffffffu) : ~k;
    return __uint_as_float(u);
}

__global__ __launch_bounds__(256) void attn_post_k(float* __restrict__ att,
                                                   const float* __restrict__ graph,
                                                   int masked, float gw)
{
    int wid = threadIdx.x >> 5, lane = threadIdx.x & 31;
    int rowIdx = blockIdx.x * 8 + wid;            // [0, HH*NB*SSQ)
    int q = rowIdx & (SSQ - 1);
    float* row = att + (size_t)rowIdx * SSQ;
    const float* grow = graph + (size_t)q * SSQ;
    int L = masked ? (q + 1) : SSQ;
    int lb = lane * 4;

    unsigned key[32];
    #pragma unroll
    for (int i = 0; i < 8; i++) {
        int pos = i * 128 + lb;
        float4 v4 = *(const float4*)&row[pos];
        key[i * 4 + 0] = (pos + 0 < L) ? f2key(v4.x) : 0u;
        key[i * 4 + 1] = (pos + 1 < L) ? f2key(v4.y) : 0u;
        key[i * 4 + 2] = (pos + 2 < L) ? f2key(v4.z) : 0u;
        key[i * 4 + 3] = (pos + 3 < L) ? f2key(v4.w) : 0u;
    }

    // warp max key (== key of max valid value, by monotonicity; L>=1 always)
    unsigned kmax = 0;
    #pragma unroll
    for (int i = 0; i < 32; i++) kmax = max(kmax, key[i]);
    kmax = __reduce_max_sync(0xffffffffu, kmax);
    float m = key2f(kmax);

    // exact top-KNN threshold: binary search on key bits, early exit at count==KNN
    unsigned threshKey = 0;
    if (L > KNN) {
        unsigned lo = 0u, hi = kmax;
        while (lo < hi) {
            unsigned mid = (unsigned)((((unsigned long long)lo + (unsigned long long)hi + 1ull)) >> 1);
            unsigned c = 0;
            #pragma unroll
            for (int i = 0; i < 32; i++) c += (key[i] >= mid) ? 1u : 0u;
            c = __reduce_add_sync(0xffffffffu, c);
            if (c == KNN) { lo = mid; break; }    // {key>=mid} == exact top-KNN set
            if (c > KNN) lo = mid; else hi = mid - 1u;
        }
        threshKey = lo;
    }

    // softmax denominator over kept (values recovered bit-exactly from keys)
    bool noTrunc = (L <= KNN);
    float s = 0.f;
    #pragma unroll
    for (int i = 0; i < 8; i++) {
        int pos = i * 128 + lb;
        #pragma unroll
        for (int j = 0; j < 4; j++) {
            unsigned k = key[i * 4 + j];
            bool kept = (pos + j < L) && (noTrunc || k >= threshKey);
            if (kept) s += expf(key2f(k) - m);
        }
    }
    #pragma unroll
    for (int o = 16; o; o >>= 1) s += __shfl_xor_sync(0xffffffffu, s, o);
    float inv = 1.0f / s;
    float og = 1.0f - gw;

    // blend + store
    #pragma unroll
    for (int i = 0; i < 8; i++) {
        int pos = i * 128 + lb;
        float4 g4 = *(const float4*)&grow[pos];
        float gv[4] = {g4.x, g4.y, g4.z, g4.w};
        float4 o4;
        float* ov = (float*)&o4;
        #pragma unroll
        for (int j = 0; j < 4; j++) {
            unsigned k = key[i * 4 + j];
            bool kept = (pos + j < L) && (noTrunc || k >= threshKey);
            float e = kept ? expf(key2f(k) - m) : 0.f;
            ov[j] = gw * gv[j] + og * (e * inv);
        }
        *(float4*)&row[pos] = o4;
    }
}

// ---------------- LayerNorm over rows of DM=512 (elementwise_affine=False) ----------------
__global__ __launch_bounds__(128) void layernorm_k(const float* __restrict__ in,
                                                   float* __restrict__ out)
{
    __shared__ float sh[4];
    int row = blockIdx.x;
    int t = threadIdx.x;
    int lane = t & 31, w = t >> 5;
    const float* rin = in + (size_t)row * DM;
    float* rout = out + (size_t)row * DM;

    float4 v4 = *(const float4*)&rin[t * 4];
    float v[4] = {v4.x, v4.y, v4.z, v4.w};

    float s = v[0] + v[1] + v[2] + v[3];
    #pragma unroll
    for (int o = 16; o; o >>= 1) s += __shfl_xor_sync(0xffffffffu, s, o);
    if (lane == 0) sh[w] = s;
    __syncthreads();
    s = sh[0] + sh[1] + sh[2] + sh[3];
    float mean = s * (1.0f / DM);
    __syncthreads();

    float sq = 0.f;
    #pragma unroll
    for (int i = 0; i < 4; i++) { float d = v[i] - mean; sq += d * d; }
    #pragma unroll
    for (int o = 16; o; o >>= 1) sq += __shfl_xor_sync(0xffffffffu, sq, o);
    if (lane == 0) sh[w] = sq;
    __syncthreads();
    sq = sh[0] + sh[1] + sh[2] + sh[3];
    float var = sq * (1.0f / DM);
    float inv = rsqrtf(var + EPS);

    float4 o4;
    o4.x = (v[0] - mean) * inv; o4.y = (v[1] - mean) * inv;
    o4.z = (v[2] - mean) * inv; o4.w = (v[3] - mean) * inv;
    *(float4*)&rout[t * 4] = o4;
}

// ---------------- host-side helpers ----------------
static inline void gemm(const float* A, const float* B, float* C,
                        int M, int Nc, int Kc, int ldc,
                        long long sAo, long long sAi, long long sBo, long long sBi,
                        long long sCo, long long sCi, int Bo, int Bi,
                        const float* bias, long long sBias,
                        const float* resid, int ldr,
                        float alpha, int transB, int relu, int causal = 0)
{
    dim3 grid(Nc / 64, M / 128, Bo * Bi), block(256);
    gemm_k<<<grid, block>>>(A, B, C, Nc, Kc, ldc, sAo, sAi, sBo, sBi, sCo, sCi, Bi,
                            bias, sBias, resid, ldr, alpha, transB, relu, causal);
}

extern "C" void kernel_launch(void* const* d_in, const int* in_sizes, int n_in,
                              void* d_out, int out_size)
{
    (void)in_sizes; (void)n_in; (void)out_size;
    const float* z        = (const float*)d_in[0];
    const float* y        = (const float*)d_in[1];
    const float* graphDec = (const float*)d_in[2];
    const float* graphEnc = (const float*)d_in[3];
    const float* dec_Wk   = (const float*)d_in[4];
    const float* dec_bk   = (const float*)d_in[5];
    const float* dec_Wv   = (const float*)d_in[6];
    const float* dec_bv   = (const float*)d_in[7];
    const float* dec_Wo   = (const float*)d_in[8];
    const float* dec_bo   = (const float*)d_in[9];
    const float* enc_Wk   = (const float*)d_in[10];
    const float* enc_bk   = (const float*)d_in[11];
    const float* enc_Wq   = (const float*)d_in[12];
    const float* enc_bq   = (const float*)d_in[13];
    const float* enc_Wv   = (const float*)d_in[14];
    const float* enc_bv   = (const float*)d_in[15];
    const float* enc_Wo   = (const float*)d_in[16];
    const float* enc_bo   = (const float*)d_in[17];
    const float* fc_W1    = (const float*)d_in[18];
    const float* fc_b1    = (const float*)d_in[19];
    const float* fc_W2    = (const float*)d_in[20];
    const float* fc_b2    = (const float*)d_in[21];
    float* out = (float*)d_out;

    float* sc = nullptr;
    cudaGetSymbolAddress((void**)&sc, g_scratch);
    float* gdec = sc + OFF_GDEC;
    float* genc = sc + OFF_GENC;
    float* gK   = sc + OFF_K;
    float* gV   = sc + OFF_V;
    float* gQ   = sc + OFF_Q;
    float* gCtx = sc + OFF_CTX;
    float* gH   = sc + OFF_H;
    float* gH2  = sc + OFF_H2;
    float* gT   = sc + OFF_T;
    float* gAtt = sc + OFF_ATT;

    const int M = NB * SSQ;               // 4096
    const long long sKh = (long long)NB * SSQ * KD;  // per-head stride in K/V/Q
    const long long sKn = (long long)SSQ * KD;       // per-batch stride
    const long long sAh = (long long)NB * SSQ * SSQ; // att per-head
    const long long sAn = (long long)SSQ * SSQ;      // att per-batch
    const float inv_scale = 0.125f;       // 1/sqrt(64)
    const int ROWS = HH * NB * SSQ;       // 32768 attention rows

    // 0) graph row-softmax
    row_softmax_k<<<SSQ, 256>>>(graphDec, gdec);
    row_softmax_k<<<SSQ, 256>>>(graphEnc, genc);

    // ---------- stage 1: masked decoder self-attention on y ----------
    gemm(y, dec_Wk, gK, M, KD, DM, KD, 0, 0, (long long)DM * KD, 0, sKh, 0, HH, 1,
         dec_bk, KD, nullptr, 0, 1.0f, 0, 0);
    gemm(y, dec_Wv, gV, M, VD, DM, VD, 0, 0, (long long)DM * VD, 0, sKh, 0, HH, 1,
         dec_bv, VD, nullptr, 0, 1.0f, 0, 0);
    gemm(gK, gK, gAtt, SSQ, SSQ, KD, SSQ, sKh, sKn, sKh, sKn, sAh, sAn, HH, NB,
         nullptr, 0, nullptr, 0, inv_scale, 1, 0, 1 /*causal skip*/);
    attn_post_k<<<ROWS / 8, 256>>>(gAtt, gdec, 1, 0.5f);
    gemm(gAtt, gV, gCtx, SSQ, VD, SSQ, DM, sAh, sAn, sKh, sKn, (long long)VD, (long long)SSQ * DM,
         HH, NB, nullptr, 0, nullptr, 0, 1.0f, 0, 0);
    gemm(gCtx, dec_Wo, gH, M, DM, DM, DM, 0, 0, 0, 0, 0, 0, 1, 1,
         dec_bo, 0, y, DM, 1.0f, 0, 0);
    layernorm_k<<<M, 128>>>(gH, gH);      // gH = h

    // ---------- stage 2: encoder-decoder attention (K,V from z, Q from h) ----------
    gemm(z, enc_Wk, gK, M, KD, DM, KD, 0, 0, (long long)DM * KD, 0, sKh, 0, HH, 1,
         enc_bk, KD, nullptr, 0, 1.0f, 0, 0);
    gemm(z, enc_Wv, gV, M, VD, DM, VD, 0, 0, (long long)DM * VD, 0, sKh, 0, HH, 1,
         enc_bv, VD, nullptr, 0, 1.0f, 0, 0);
    gemm(gH, enc_Wq, gQ, M, KD, DM, KD, 0, 0, (long long)DM * KD, 0, sKh, 0, HH, 1,
         enc_bq, KD, nullptr, 0, 1.0f, 0, 0);
    gemm(gQ, gK, gAtt, SSQ, SSQ, KD, SSQ, sKh, sKn, sKh, sKn, sAh, sAn, HH, NB,
         nullptr, 0, nullptr, 0, inv_scale, 1, 0);
    attn_post_k<<<ROWS / 8, 256>>>(gAtt, genc, 0, 0.5f);
    gemm(gAtt, gV, gCtx, SSQ, VD, SSQ, DM, sAh, sAn, sKh, sKn, (long long)VD, (long long)SSQ * DM,
         HH, NB, nullptr, 0, nullptr, 0, 1.0f, 0, 0);
    gemm(gCtx, enc_Wo, gH2, M, DM, DM, DM, 0, 0, 0, 0, 0, 0, 1, 1,
         enc_bo, 0, gH, DM, 1.0f, 0, 0);
    layernorm_k<<<M, 128>>>(gH2, gH2);    // gH2 = h2

    // ---------- stage 3: MLP ----------
    gemm(gH2, fc_W1, gT, M, FCD, DM, FCD, 0, 0, 0, 0, 0, 0, 1, 1,
         fc_b1, 0, nullptr, 0, 1.0f, 0, 1);                 // relu
    gemm(gT, fc_W2, gH, M, DM, FCD, DM, 0, 0, 0, 0, 0, 0, 1, 1,
         fc_b2, 0, gH2, DM, 1.0f, 0, 0);                    // + residual h2
    layernorm_k<<<M, 128>>>(gH, out);
}